// round 10
// baseline (speedup 1.0000x reference)
#include <cuda_runtime.h>
#include <cuda_fp16.h>

#define NP   400000
#define CH   32
#define KK   27
#define TPB  256
#define TILE 256
#define NT   ((NP + TILE - 1) / TILE)   // 1563
#define BT   256
#define NT2  ((NP + BT - 1) / BT)

// ---- device scratch (allocation-free rule) ----
__device__ float g_buf1[(size_t)NP*CH];
__device__ float g_buf2[(size_t)NP*CH];
__device__ float g_stats[128];                   // [0:64) conv1 sum/sumsq, [64:128) conv2
__device__ unsigned short g_wt[2][KK*1024];      // per-k 2KB fp16 W tiles, swizzled
__device__ unsigned g_pk[((size_t)NP+1)*16];     // packed fp16 rows 64B; row NP = zeros
__device__ int g_fidx[(size_t)KK*NP];            // k-major folded idx (mask applied; NP = inactive)

// ---- conv smem layout (bytes) ----
#define SM_W   0                        // 27*2048 = 55296
#define SM_ST  55296                    // 64 floats
#define SM_TOT (SM_ST + 256)            // 55552 -> 2 CTAs/SM

// ============ helpers ============
__device__ __forceinline__ unsigned smem_u32(const void* p){
    unsigned a; asm("{ .reg .u64 t; cvta.to.shared.u64 t, %1; cvt.u32.u64 %0, t; }"
                    : "=r"(a) : "l"(p));
    return a;
}
__device__ __forceinline__ void ldmx4t(unsigned* r, unsigned addr){
    asm volatile("ldmatrix.sync.aligned.m8n8.x4.trans.shared.b16 {%0,%1,%2,%3}, [%4];"
        : "=r"(r[0]),"=r"(r[1]),"=r"(r[2]),"=r"(r[3]) : "r"(addr));
}
__device__ __forceinline__ void mma16816h(float* d,
    unsigned a0, unsigned a1, unsigned a2, unsigned a3,
    unsigned b0, unsigned b1)
{
    asm volatile("mma.sync.aligned.m16n8k16.row.col.f32.f16.f16.f32 "
        "{%0,%1,%2,%3}, {%4,%5,%6,%7}, {%8,%9}, {%0,%1,%2,%3};"
        : "+f"(d[0]),"+f"(d[1]),"+f"(d[2]),"+f"(d[3])
        : "r"(a0),"r"(a1),"r"(a2),"r"(a3), "r"(b0),"r"(b1));
}
__device__ __forceinline__ unsigned pack_f16(float x, float y){
    __half2 h = __floats2half2_rn(x, y);
    return *(unsigned*)&h;
}

// ============ W prep: fp32 -> swizzled fp16 tiles (B operand) ============
__global__ void prep_w(const float* __restrict__ W1, const float* __restrict__ W2){
    int idx = blockIdx.x*blockDim.x + threadIdx.x;
    if (idx >= 2*KK*CH*CH) return;
    int w   = idx / (KK*CH*CH);
    int rem = idx % (KK*CH*CH);
    int k = rem / (CH*CH);
    int i = (rem / CH) % CH;   // input channel  (GEMM K)  -> row
    int c = rem % CH;          // output channel (GEMM N)  -> col
    float v = (w ? W2 : W1)[(k*CH + i)*CH + c];
    unsigned off = i*64 + ((((unsigned)(c>>3)) ^ ((i>>1)&3)) << 4) + (c&7)*2;
    g_wt[w][k*1024 + (off>>1)] = __half_as_ushort(__float2half_rn(v));
}

__global__ void zero_stats(){
    if (threadIdx.x < 128) g_stats[threadIdx.x] = 0.f;
    if (threadIdx.x < 16)  g_pk[(size_t)NP*16 + threadIdx.x] = 0u;   // zero sentinel row
}

// ============ idx transpose: (n,k) row-major + mask -> k-major folded ============
__global__ void prep_fidx(const int* __restrict__ nbr, const int* __restrict__ mask,
                          int* __restrict__ fidx)
{
    __shared__ int tmp[KK][BT + 1];
    long long gbase = (long long)blockIdx.x * BT * KK;
    for (int j = threadIdx.x; j < BT*KK; j += blockDim.x){
        long long g = gbase + j;
        int v = NP;
        if (g < (long long)NP*KK && mask[g]) v = nbr[g];
        int nl = j / KK, k = j - nl*KK;
        tmp[k][nl] = v;
    }
    __syncthreads();
    int n = blockIdx.x*BT + threadIdx.x;
    if (n < NP){
        #pragma unroll 1
        for (int k = 0; k < KK; k++) fidx[(size_t)k*NP + n] = tmp[k][threadIdx.x];
    }
}

// ============ pack input: fp32 row -> 16 fp16-pair words, permuted word order ============
__global__ void pack_input(const float* __restrict__ src, unsigned* __restrict__ dst,
                           int bn, const float* __restrict__ gam, const float* __restrict__ bet)
{
    long long t = (long long)blockIdx.x*blockDim.x + threadIdx.x;
    if (t >= (long long)NP*16) return;
    int q   = (int)(t & 15);
    long long row = t >> 4;
    int p = (q >> 2) + 4*(q & 3);
    int c = 2*p;
    float2 v = *(const float2*)(src + row*CH + c);
    float x = v.x, y = v.y;
    if (bn){
        float m0 = g_stats[c]   * (1.f/NP), m1 = g_stats[c+1]   * (1.f/NP);
        float q0 = g_stats[32+c]* (1.f/NP), q1 = g_stats[32+c+1]* (1.f/NP);
        float s0 = rsqrtf(q0 - m0*m0 + 1e-5f) * gam[c];
        float s1 = rsqrtf(q1 - m1*m1 + 1e-5f) * gam[c+1];
        x = fmaxf(x*s0 + (bet[c]   - m0*s0), 0.f);
        y = fmaxf(y*s1 + (bet[c+1] - m1*s1), 0.f);
    }
    dst[row*16 + q] = pack_f16(x, y);
}

// ============ conv: fp16 single-term, depth-3 register pipeline ============
__global__ void __launch_bounds__(TPB,2) conv_mma(
    const unsigned char* __restrict__ pk, const unsigned short* __restrict__ wt,
    const int* __restrict__ fidx, float* __restrict__ out, int stats_off)
{
    extern __shared__ char smem[];
    const unsigned sb = smem_u32(smem);
    const int tid = threadIdx.x, w = tid >> 5, lane = tid & 31;
    const int gq = lane & 3, r_lo = lane >> 2;
    const int rbase = blockIdx.x*TILE + w*32 + r_lo;

    if (tid < 64) ((float*)(smem + SM_ST))[tid] = 0.f;
    // W tiles -> smem (55296B)
    {
        const uint4* s = (const uint4*)wt;
        uint4* d = (uint4*)(smem + SM_W);
        #pragma unroll 1
        for (int i = tid; i < (KK*2048)/16; i += TPB) d[i] = s[i];
    }
    __syncthreads();

    const int k0 = (w*27) >> 3;          // warp k-rotation (8 warps)
    int nrow[4];
    #pragma unroll
    for (int m = 0; m < 4; m++){ int n = rbase + m*8; nrow[m] = (n < NP) ? n : -1; }

    uint4 vh[3][4];
    int irC[4];

    // ---- prologue: issue stages j=0,1,2; preload idx for j=3 ----
    #pragma unroll
    for (int j = 0; j < 3; j++){
        int kk = k0 + j; if (kk >= KK) kk -= KK;
        #pragma unroll
        for (int m = 0; m < 4; m++){
            int ir = (nrow[m] >= 0) ? fidx[(size_t)kk*NP + nrow[m]] : NP;
            vh[j][m] = *(const uint4*)(pk + (size_t)ir*64 + gq*16);
        }
    }
    {
        int kk = k0 + 3; if (kk >= KK) kk -= KK;
        #pragma unroll
        for (int m = 0; m < 4; m++)
            irC[m] = (nrow[m] >= 0) ? fidx[(size_t)kk*NP + nrow[m]] : NP;
    }

    float acc[2][4][4];
    #pragma unroll
    for (int a = 0; a < 2; a++)
        #pragma unroll
        for (int b = 0; b < 4; b++)
            #pragma unroll
            for (int c = 0; c < 4; c++) acc[a][b][c] = 0.f;

    int buf = 0;
    #pragma unroll 3
    for (int j = 0; j < KK; j++){
        int kk = k0 + j; if (kk >= KK) kk -= KK;

        // keep current buffer's words (register rename; no copies needed)
        const unsigned* q0 = (const unsigned*)&vh[buf][0];
        const unsigned* q1 = (const unsigned*)&vh[buf][1];
        const unsigned* q2 = (const unsigned*)&vh[buf][2];
        const unsigned* q3 = (const unsigned*)&vh[buf][3];
        unsigned a00=q0[0],a01=q0[1],a02=q0[2],a03=q0[3];
        unsigned a10=q1[0],a11=q1[1],a12=q1[2],a13=q1[3];
        unsigned a20=q2[0],a21=q2[1],a22=q2[2],a23=q2[3];
        unsigned a30=q3[0],a31=q3[1],a32=q3[2],a33=q3[3];

        // ---- issue j+3 into freed buffer ----
        if (j + 3 < KK){
            #pragma unroll
            for (int m = 0; m < 4; m++)
                vh[buf][m] = *(const uint4*)(pk + (size_t)irC[m]*64 + gq*16);
        }
        // ---- preload idx for j+4 ----
        if (j + 4 < KK){
            int k4 = k0 + j + 4; if (k4 >= KK) k4 -= KK;
            #pragma unroll
            for (int m = 0; m < 4; m++)
                irC[m] = (nrow[m] >= 0) ? fidx[(size_t)k4*NP + nrow[m]] : NP;
        }

        // ---- B per-nq + 16 mma (A words passed directly) ----
        const unsigned wk = sb + SM_W + kk*2048;
        #pragma unroll
        for (int nq = 0; nq < 4; nq++){
            unsigned bh[4];
            unsigned sw = ((((unsigned)nq) ^ ((lane>>1)&3)) << 4);
            ldmx4t(bh, wk + lane*64 + sw);
            // rb=0: rows from vh[0],vh[1]
            mma16816h(acc[0][nq], a00, a10, a01, a11, bh[0], bh[1]);
            mma16816h(acc[0][nq], a02, a12, a03, a13, bh[2], bh[3]);
            // rb=1: rows from vh[2],vh[3]
            mma16816h(acc[1][nq], a20, a30, a21, a31, bh[0], bh[1]);
            mma16816h(acc[1][nq], a22, a32, a23, a33, bh[2], bh[3]);
        }
        if (++buf == 3) buf = 0;
    }

    // ---- epilogue: store raw conv output + fused BN stats ----
    float sR[8], qR[8];
    #pragma unroll
    for (int i = 0; i < 8; i++){ sR[i] = 0.f; qR[i] = 0.f; }

    const int C0 = gq * 2;
    #pragma unroll
    for (int rb = 0; rb < 2; rb++){
        #pragma unroll
        for (int nq = 0; nq < 4; nq++){
            float a0 = acc[rb][nq][0], a1 = acc[rb][nq][1];
            float a2 = acc[rb][nq][2], a3 = acc[rb][nq][3];
            int m0 = rbase + rb*16, m1 = m0 + 8;
            int c  = nq*8 + C0;
            if (m0 < NP) *(float2*)(out + (size_t)m0*CH + c) = make_float2(a0, a1);
            if (m1 < NP) *(float2*)(out + (size_t)m1*CH + c) = make_float2(a2, a3);
            sR[nq*2+0] += a0 + a2;  qR[nq*2+0] += a0*a0 + a2*a2;
            sR[nq*2+1] += a1 + a3;  qR[nq*2+1] += a1*a1 + a3*a3;
        }
    }
    #pragma unroll
    for (int i = 0; i < 8; i++){
        #pragma unroll
        for (int off = 4; off < 32; off <<= 1){
            sR[i] += __shfl_xor_sync(0xffffffffu, sR[i], off);
            qR[i] += __shfl_xor_sync(0xffffffffu, qR[i], off);
        }
    }
    if (lane < 4){
        float* st = (float*)(smem + SM_ST);
        #pragma unroll
        for (int nq = 0; nq < 4; nq++){
            atomicAdd(&st[     nq*8 + lane*2    ], sR[nq*2+0]);
            atomicAdd(&st[     nq*8 + lane*2 + 1], sR[nq*2+1]);
            atomicAdd(&st[32 + nq*8 + lane*2    ], qR[nq*2+0]);
            atomicAdd(&st[32 + nq*8 + lane*2 + 1], qR[nq*2+1]);
        }
    }
    __syncthreads();
    if (tid < 64) atomicAdd(&g_stats[stats_off + tid], ((float*)(smem + SM_ST))[tid]);
}

// ---- final BN + residual + ReLU ----
__global__ void bnrelu_kernel(const float4* __restrict__ x, int stats_off,
    const float* __restrict__ gamma, const float* __restrict__ beta,
    const float4* __restrict__ res, float4* __restrict__ out)
{
    long long i = (long long)blockIdx.x*blockDim.x + threadIdx.x;
    if (i >= (long long)NP*CH/4) return;
    int c0 = (int)(i & 7) * 4;
    const float invN = 1.0f / NP;
    float4 v = x[i];
    float4 r4 = res[i];
    float4 o;
#define BN_ONE(comp, c) { \
        float mean = g_stats[stats_off + c0 + c] * invN; \
        float var  = g_stats[stats_off + 32 + c0 + c] * invN - mean*mean; \
        float sc   = rsqrtf(var + 1e-5f) * gamma[c0 + c]; \
        float val  = (v.comp - mean)*sc + beta[c0 + c] + r4.comp; \
        o.comp = fmaxf(val, 0.f); }
    BN_ONE(x, 0) BN_ONE(y, 1) BN_ONE(z, 2) BN_ONE(w, 3)
#undef BN_ONE
    out[i] = o;
}

extern "C" void kernel_launch(void* const* d_in, const int* in_sizes, int n_in,
                              void* d_out, int out_size)
{
    const float* feats  = (const float*)d_in[0];
    const float* W1     = (const float*)d_in[1];
    const float* gamma1 = (const float*)d_in[2];
    const float* beta1  = (const float*)d_in[3];
    const float* W2     = (const float*)d_in[4];
    const float* gamma2 = (const float*)d_in[5];
    const float* beta2  = (const float*)d_in[6];
    const int*   nbr    = (const int*)d_in[7];
    const int*   mask   = (const int*)d_in[8];
    float* out = (float*)d_out;

    float *buf1, *buf2; unsigned short* wt; unsigned* pk; int* fidx;
    cudaGetSymbolAddress((void**)&buf1, g_buf1);
    cudaGetSymbolAddress((void**)&buf2, g_buf2);
    cudaGetSymbolAddress((void**)&wt,   g_wt);
    cudaGetSymbolAddress((void**)&pk,   g_pk);
    cudaGetSymbolAddress((void**)&fidx, g_fidx);

    cudaFuncSetAttribute(conv_mma, cudaFuncAttributeMaxDynamicSharedMemorySize, SM_TOT);

    const long long ne4 = (long long)NP*CH/4;
    const int gridb = (int)((ne4 + 255) / 256);
    const int gridp = (int)(((long long)NP*16 + 255) / 256);

    zero_stats<<<1,128>>>();
    prep_w<<<(2*KK*CH*CH + 255)/256, 256>>>(W1, W2);
    prep_fidx<<<NT2, 256>>>(nbr, mask, fidx);
    // pack feats -> pk; conv1: raw -> buf1, stats@0
    pack_input<<<gridp, 256>>>(feats, pk, 0, (const float*)0, (const float*)0);
    conv_mma<<<NT, TPB, SM_TOT>>>((const unsigned char*)pk, wt, fidx, buf1, 0);
    // h = relu(bn1(buf1)) packed -> pk; conv2: raw -> buf2, stats@64
    pack_input<<<gridp, 256>>>(buf1, pk, 1, gamma1, beta1);
    conv_mma<<<NT, TPB, SM_TOT>>>((const unsigned char*)pk, wt + KK*1024, fidx, buf2, 64);
    // out = relu(BN2(buf2) + feats)
    bnrelu_kernel<<<gridb, 256>>>((const float4*)buf2, 64, gamma2, beta2,
                                  (const float4*)feats, (float4*)out);
}

// round 11
// speedup vs baseline: 1.0517x; 1.0517x over previous
#include <cuda_runtime.h>
#include <cuda_fp16.h>

#define NP   400000
#define CH   32
#define KK   27
#define TPB  256
#define TILE 256
#define NT   ((NP + TILE - 1) / TILE)   // 1563
#define BT   256
#define NT2  ((NP + BT - 1) / BT)

// ---- device scratch (allocation-free rule) ----
__device__ float g_buf1[(size_t)NP*CH];
__device__ float g_buf2[(size_t)NP*CH];
__device__ float g_stats[128];                   // [0:64) conv1 sum/sumsq, [64:128) conv2
__device__ unsigned short g_wt[2][KK*1024];      // per-k 2KB fp16 W tiles, swizzled
__device__ unsigned g_pk[((size_t)NP+1)*16];     // packed fp16 rows 64B; row NP = zeros
__device__ int g_fidx[(size_t)KK*NP];            // k-major folded idx (mask applied; NP = inactive)

// ---- conv smem layout (bytes) ----
#define SM_W   0                        // 27*2048 = 55296
#define SM_ST  55296                    // 64 floats
#define SM_TOT (SM_ST + 256)            // 55552 -> 2 CTAs/SM

// ============ helpers ============
__device__ __forceinline__ unsigned smem_u32(const void* p){
    unsigned a; asm("{ .reg .u64 t; cvta.to.shared.u64 t, %1; cvt.u32.u64 %0, t; }"
                    : "=r"(a) : "l"(p));
    return a;
}
__device__ __forceinline__ void ldmx4t(unsigned* r, unsigned addr){
    asm volatile("ldmatrix.sync.aligned.m8n8.x4.trans.shared.b16 {%0,%1,%2,%3}, [%4];"
        : "=r"(r[0]),"=r"(r[1]),"=r"(r[2]),"=r"(r[3]) : "r"(addr));
}
__device__ __forceinline__ void mma16816h(float* d,
    unsigned a0, unsigned a1, unsigned a2, unsigned a3,
    unsigned b0, unsigned b1)
{
    asm volatile("mma.sync.aligned.m16n8k16.row.col.f32.f16.f16.f32 "
        "{%0,%1,%2,%3}, {%4,%5,%6,%7}, {%8,%9}, {%0,%1,%2,%3};"
        : "+f"(d[0]),"+f"(d[1]),"+f"(d[2]),"+f"(d[3])
        : "r"(a0),"r"(a1),"r"(a2),"r"(a3), "r"(b0),"r"(b1));
}
__device__ __forceinline__ unsigned pack_f16(float x, float y){
    __half2 h = __floats2half2_rn(x, y);
    return *(unsigned*)&h;
}

// ============ W prep: fp32 -> swizzled fp16 tiles (B operand) ============
__global__ void prep_w(const float* __restrict__ W1, const float* __restrict__ W2){
    int idx = blockIdx.x*blockDim.x + threadIdx.x;
    if (idx >= 2*KK*CH*CH) return;
    int w   = idx / (KK*CH*CH);
    int rem = idx % (KK*CH*CH);
    int k = rem / (CH*CH);
    int i = (rem / CH) % CH;   // input channel  (GEMM K)  -> row
    int c = rem % CH;          // output channel (GEMM N)  -> col
    float v = (w ? W2 : W1)[(k*CH + i)*CH + c];
    unsigned off = i*64 + ((((unsigned)(c>>3)) ^ ((i>>1)&3)) << 4) + (c&7)*2;
    g_wt[w][k*1024 + (off>>1)] = __half_as_ushort(__float2half_rn(v));
}

__global__ void zero_stats(){
    if (threadIdx.x < 128) g_stats[threadIdx.x] = 0.f;
    if (threadIdx.x < 16)  g_pk[(size_t)NP*16 + threadIdx.x] = 0u;   // zero sentinel row
}

// ============ idx transpose: (n,k) row-major + mask -> k-major folded ============
__global__ void prep_fidx(const int* __restrict__ nbr, const int* __restrict__ mask,
                          int* __restrict__ fidx)
{
    __shared__ int tmp[KK][BT + 1];
    long long gbase = (long long)blockIdx.x * BT * KK;
    for (int j = threadIdx.x; j < BT*KK; j += blockDim.x){
        long long g = gbase + j;
        int v = NP;
        if (g < (long long)NP*KK && mask[g]) v = nbr[g];
        int nl = j / KK, k = j - nl*KK;
        tmp[k][nl] = v;
    }
    __syncthreads();
    int n = blockIdx.x*BT + threadIdx.x;
    if (n < NP){
        #pragma unroll 1
        for (int k = 0; k < KK; k++) fidx[(size_t)k*NP + n] = tmp[k][threadIdx.x];
    }
}

// ============ pack input: fp32 row -> 16 fp16-pair words, permuted word order ============
__global__ void pack_input(const float* __restrict__ src, unsigned* __restrict__ dst,
                           int bn, const float* __restrict__ gam, const float* __restrict__ bet)
{
    long long t = (long long)blockIdx.x*blockDim.x + threadIdx.x;
    if (t >= (long long)NP*16) return;
    int q   = (int)(t & 15);
    long long row = t >> 4;
    int p = (q >> 2) + 4*(q & 3);
    int c = 2*p;
    float2 v = *(const float2*)(src + row*CH + c);
    float x = v.x, y = v.y;
    if (bn){
        float m0 = g_stats[c]   * (1.f/NP), m1 = g_stats[c+1]   * (1.f/NP);
        float q0 = g_stats[32+c]* (1.f/NP), q1 = g_stats[32+c+1]* (1.f/NP);
        float s0 = rsqrtf(q0 - m0*m0 + 1e-5f) * gam[c];
        float s1 = rsqrtf(q1 - m1*m1 + 1e-5f) * gam[c+1];
        x = fmaxf(x*s0 + (bet[c]   - m0*s0), 0.f);
        y = fmaxf(y*s1 + (bet[c+1] - m1*s1), 0.f);
    }
    dst[row*16 + q] = pack_f16(x, y);
}

// ============ conv: fp16 single-term, depth-3 pipeline (static buffer names) ============
__global__ void __launch_bounds__(TPB,2) conv_mma(
    const unsigned char* __restrict__ pk, const unsigned short* __restrict__ wt,
    const int* __restrict__ fidx, float* __restrict__ out, int stats_off)
{
    extern __shared__ char smem[];
    const unsigned sb = smem_u32(smem);
    const int tid = threadIdx.x, w = tid >> 5, lane = tid & 31;
    const int gq = lane & 3, r_lo = lane >> 2;
    const int rbase = blockIdx.x*TILE + w*32 + r_lo;

    if (tid < 64) ((float*)(smem + SM_ST))[tid] = 0.f;
    // W tiles -> smem (55296B)
    {
        const uint4* s = (const uint4*)wt;
        uint4* d = (uint4*)(smem + SM_W);
        #pragma unroll 1
        for (int i = tid; i < (KK*2048)/16; i += TPB) d[i] = s[i];
    }
    __syncthreads();

    const int k0 = (w*27) >> 3;          // warp k-rotation (8 warps)
    int nrow[4];
    #pragma unroll
    for (int m = 0; m < 4; m++){ int n = rbase + m*8; nrow[m] = (n < NP) ? n : -1; }

    uint4 vh0[4], vh1[4], vh2[4];
    int irC[4];

    // ---- prologue: load j=0,1,2 into vh0/vh1/vh2; preload idx for j=3 ----
    {
        int kk0 = k0;             if (kk0 >= KK) kk0 -= KK;
        int kk1 = k0 + 1;         if (kk1 >= KK) kk1 -= KK;
        int kk2 = k0 + 2;         if (kk2 >= KK) kk2 -= KK;
        #pragma unroll
        for (int m = 0; m < 4; m++){
            int i0 = (nrow[m] >= 0) ? fidx[(size_t)kk0*NP + nrow[m]] : NP;
            int i1 = (nrow[m] >= 0) ? fidx[(size_t)kk1*NP + nrow[m]] : NP;
            int i2 = (nrow[m] >= 0) ? fidx[(size_t)kk2*NP + nrow[m]] : NP;
            vh0[m] = *(const uint4*)(pk + (size_t)i0*64 + gq*16);
            vh1[m] = *(const uint4*)(pk + (size_t)i1*64 + gq*16);
            vh2[m] = *(const uint4*)(pk + (size_t)i2*64 + gq*16);
        }
        int kk3 = k0 + 3; if (kk3 >= KK) kk3 -= KK;
        #pragma unroll
        for (int m = 0; m < 4; m++)
            irC[m] = (nrow[m] >= 0) ? fidx[(size_t)kk3*NP + nrow[m]] : NP;
    }

    float acc[2][4][4];
    #pragma unroll
    for (int a = 0; a < 2; a++)
        #pragma unroll
        for (int b = 0; b < 4; b++)
            #pragma unroll
            for (int c = 0; c < 4; c++) acc[a][b][c] = 0.f;

#define CONV_BODY(VH, J)                                                          \
    {                                                                             \
        int kk = k0 + (J); if (kk >= KK) kk -= KK;                                \
        unsigned a00=VH[0].x, a01=VH[0].y, a02=VH[0].z, a03=VH[0].w;              \
        unsigned a10=VH[1].x, a11=VH[1].y, a12=VH[1].z, a13=VH[1].w;              \
        unsigned a20=VH[2].x, a21=VH[2].y, a22=VH[2].z, a23=VH[2].w;              \
        unsigned a30=VH[3].x, a31=VH[3].y, a32=VH[3].z, a33=VH[3].w;              \
        if ((J) + 3 < KK){                                                        \
            _Pragma("unroll")                                                     \
            for (int m = 0; m < 4; m++)                                           \
                VH[m] = *(const uint4*)(pk + (size_t)irC[m]*64 + gq*16);          \
        }                                                                         \
        if ((J) + 4 < KK){                                                        \
            int k4 = k0 + (J) + 4; if (k4 >= KK) k4 -= KK;                        \
            _Pragma("unroll")                                                     \
            for (int m = 0; m < 4; m++)                                           \
                irC[m] = (nrow[m] >= 0) ? fidx[(size_t)k4*NP + nrow[m]] : NP;     \
        }                                                                         \
        const unsigned wk = sb + SM_W + kk*2048;                                  \
        _Pragma("unroll")                                                         \
        for (int nq = 0; nq < 4; nq++){                                           \
            unsigned bh[4];                                                       \
            unsigned sw = ((((unsigned)nq) ^ ((lane>>1)&3)) << 4);                \
            ldmx4t(bh, wk + lane*64 + sw);                                        \
            mma16816h(acc[0][nq], a00, a10, a01, a11, bh[0], bh[1]);              \
            mma16816h(acc[0][nq], a02, a12, a03, a13, bh[2], bh[3]);              \
            mma16816h(acc[1][nq], a20, a30, a21, a31, bh[0], bh[1]);              \
            mma16816h(acc[1][nq], a22, a32, a23, a33, bh[2], bh[3]);              \
        }                                                                         \
    }

    #pragma unroll 1
    for (int jj = 0; jj < KK; jj += 3){
        CONV_BODY(vh0, jj + 0);
        CONV_BODY(vh1, jj + 1);
        CONV_BODY(vh2, jj + 2);
    }
#undef CONV_BODY

    // ---- epilogue: store raw conv output + fused BN stats ----
    float sR[8], qR[8];
    #pragma unroll
    for (int i = 0; i < 8; i++){ sR[i] = 0.f; qR[i] = 0.f; }

    const int C0 = gq * 2;
    #pragma unroll
    for (int rb = 0; rb < 2; rb++){
        #pragma unroll
        for (int nq = 0; nq < 4; nq++){
            float a0 = acc[rb][nq][0], a1 = acc[rb][nq][1];
            float a2 = acc[rb][nq][2], a3 = acc[rb][nq][3];
            int m0 = rbase + rb*16, m1 = m0 + 8;
            int c  = nq*8 + C0;
            if (m0 < NP) *(float2*)(out + (size_t)m0*CH + c) = make_float2(a0, a1);
            if (m1 < NP) *(float2*)(out + (size_t)m1*CH + c) = make_float2(a2, a3);
            sR[nq*2+0] += a0 + a2;  qR[nq*2+0] += a0*a0 + a2*a2;
            sR[nq*2+1] += a1 + a3;  qR[nq*2+1] += a1*a1 + a3*a3;
        }
    }
    #pragma unroll
    for (int i = 0; i < 8; i++){
        #pragma unroll
        for (int off = 4; off < 32; off <<= 1){
            sR[i] += __shfl_xor_sync(0xffffffffu, sR[i], off);
            qR[i] += __shfl_xor_sync(0xffffffffu, qR[i], off);
        }
    }
    if (lane < 4){
        float* st = (float*)(smem + SM_ST);
        #pragma unroll
        for (int nq = 0; nq < 4; nq++){
            atomicAdd(&st[     nq*8 + lane*2    ], sR[nq*2+0]);
            atomicAdd(&st[     nq*8 + lane*2 + 1], sR[nq*2+1]);
            atomicAdd(&st[32 + nq*8 + lane*2    ], qR[nq*2+0]);
            atomicAdd(&st[32 + nq*8 + lane*2 + 1], qR[nq*2+1]);
        }
    }
    __syncthreads();
    if (tid < 64) atomicAdd(&g_stats[stats_off + tid], ((float*)(smem + SM_ST))[tid]);
}

// ---- final BN + residual + ReLU ----
__global__ void bnrelu_kernel(const float4* __restrict__ x, int stats_off,
    const float* __restrict__ gamma, const float* __restrict__ beta,
    const float4* __restrict__ res, float4* __restrict__ out)
{
    long long i = (long long)blockIdx.x*blockDim.x + threadIdx.x;
    if (i >= (long long)NP*CH/4) return;
    int c0 = (int)(i & 7) * 4;
    const float invN = 1.0f / NP;
    float4 v = x[i];
    float4 r4 = res[i];
    float4 o;
#define BN_ONE(comp, c) { \
        float mean = g_stats[stats_off + c0 + c] * invN; \
        float var  = g_stats[stats_off + 32 + c0 + c] * invN - mean*mean; \
        float sc   = rsqrtf(var + 1e-5f) * gamma[c0 + c]; \
        float val  = (v.comp - mean)*sc + beta[c0 + c] + r4.comp; \
        o.comp = fmaxf(val, 0.f); }
    BN_ONE(x, 0) BN_ONE(y, 1) BN_ONE(z, 2) BN_ONE(w, 3)
#undef BN_ONE
    out[i] = o;
}

extern "C" void kernel_launch(void* const* d_in, const int* in_sizes, int n_in,
                              void* d_out, int out_size)
{
    const float* feats  = (const float*)d_in[0];
    const float* W1     = (const float*)d_in[1];
    const float* gamma1 = (const float*)d_in[2];
    const float* beta1  = (const float*)d_in[3];
    const float* W2     = (const float*)d_in[4];
    const float* gamma2 = (const float*)d_in[5];
    const float* beta2  = (const float*)d_in[6];
    const int*   nbr    = (const int*)d_in[7];
    const int*   mask   = (const int*)d_in[8];
    float* out = (float*)d_out;

    float *buf1, *buf2; unsigned short* wt; unsigned* pk; int* fidx;
    cudaGetSymbolAddress((void**)&buf1, g_buf1);
    cudaGetSymbolAddress((void**)&buf2, g_buf2);
    cudaGetSymbolAddress((void**)&wt,   g_wt);
    cudaGetSymbolAddress((void**)&pk,   g_pk);
    cudaGetSymbolAddress((void**)&fidx, g_fidx);

    cudaFuncSetAttribute(conv_mma, cudaFuncAttributeMaxDynamicSharedMemorySize, SM_TOT);

    const long long ne4 = (long long)NP*CH/4;
    const int gridb = (int)((ne4 + 255) / 256);
    const int gridp = (int)(((long long)NP*16 + 255) / 256);

    // NOTE: zero_stats launched twice (idempotent) so conv1 is the 6th launch
    // and lands under ncu's -s 5 -c 1 window.
    zero_stats<<<1,128>>>();
    zero_stats<<<1,128>>>();
    prep_w<<<(2*KK*CH*CH + 255)/256, 256>>>(W1, W2);
    prep_fidx<<<NT2, 256>>>(nbr, mask, fidx);
    // pack feats -> pk; conv1: raw -> buf1, stats@0
    pack_input<<<gridp, 256>>>(feats, pk, 0, (const float*)0, (const float*)0);
    conv_mma<<<NT, TPB, SM_TOT>>>((const unsigned char*)pk, wt, fidx, buf1, 0);
    // h = relu(bn1(buf1)) packed -> pk; conv2: raw -> buf2, stats@64
    pack_input<<<gridp, 256>>>(buf1, pk, 1, gamma1, beta1);
    conv_mma<<<NT, TPB, SM_TOT>>>((const unsigned char*)pk, wt + KK*1024, fidx, buf2, 64);
    // out = relu(BN2(buf2) + feats)
    bnrelu_kernel<<<gridb, 256>>>((const float4*)buf2, 64, gamma2, beta2,
                                  (const float4*)feats, (float4*)out);
}

// round 12
// speedup vs baseline: 1.3510x; 1.2846x over previous
#include <cuda_runtime.h>
#include <cuda_fp16.h>

#define NP   400000
#define CH   32
#define KK   27
#define TPB  256
#define TILE 256
#define NT   ((NP + TILE - 1) / TILE)   // 1563
#define BT   256
#define NT2  ((NP + BT - 1) / BT)

// ---- device scratch (allocation-free rule) ----
__device__ float g_buf1[(size_t)NP*CH];
__device__ float g_buf2[(size_t)NP*CH];
__device__ float g_stats[128];                   // [0:64) conv1 sum/sumsq, [64:128) conv2
__device__ unsigned short g_wt[2][KK*1024];      // per-k 2KB fp16 W tiles, swizzled
__device__ unsigned g_pk[((size_t)NP+1)*16];     // packed fp16 rows 64B; row NP = zeros
__device__ int g_fidx[(size_t)KK*NP];            // k-major folded idx (mask applied; NP = inactive)

// ---- conv smem layout (bytes) ----
#define SM_W   0                        // 27*2048 = 55296
#define SM_ST  55296                    // 64 floats
#define SM_TOT (SM_ST + 256)            // 55552 -> 2 CTAs/SM

// ============ helpers ============
__device__ __forceinline__ unsigned smem_u32(const void* p){
    unsigned a; asm("{ .reg .u64 t; cvta.to.shared.u64 t, %1; cvt.u32.u64 %0, t; }"
                    : "=r"(a) : "l"(p));
    return a;
}
__device__ __forceinline__ void ldmx4t(unsigned* r, unsigned addr){
    asm volatile("ldmatrix.sync.aligned.m8n8.x4.trans.shared.b16 {%0,%1,%2,%3}, [%4];"
        : "=r"(r[0]),"=r"(r[1]),"=r"(r[2]),"=r"(r[3]) : "r"(addr));
}
__device__ __forceinline__ void mma16816h(float* d, const unsigned* a, const unsigned* b){
    asm volatile("mma.sync.aligned.m16n8k16.row.col.f32.f16.f16.f32 "
        "{%0,%1,%2,%3}, {%4,%5,%6,%7}, {%8,%9}, {%0,%1,%2,%3};"
        : "+f"(d[0]),"+f"(d[1]),"+f"(d[2]),"+f"(d[3])
        : "r"(a[0]),"r"(a[1]),"r"(a[2]),"r"(a[3]), "r"(b[0]),"r"(b[1]));
}
__device__ __forceinline__ unsigned pack_f16(float x, float y){
    __half2 h = __floats2half2_rn(x, y);
    return *(unsigned*)&h;
}

// ============ W prep: fp32 -> swizzled fp16 tiles (B operand) ============
__global__ void prep_w(const float* __restrict__ W1, const float* __restrict__ W2){
    int idx = blockIdx.x*blockDim.x + threadIdx.x;
    if (idx >= 2*KK*CH*CH) return;
    int w   = idx / (KK*CH*CH);
    int rem = idx % (KK*CH*CH);
    int k = rem / (CH*CH);
    int i = (rem / CH) % CH;   // input channel  (GEMM K)  -> row
    int c = rem % CH;          // output channel (GEMM N)  -> col
    float v = (w ? W2 : W1)[(k*CH + i)*CH + c];
    unsigned off = i*64 + ((((unsigned)(c>>3)) ^ ((i>>1)&3)) << 4) + (c&7)*2;
    g_wt[w][k*1024 + (off>>1)] = __half_as_ushort(__float2half_rn(v));
}

__global__ void zero_stats(){
    if (threadIdx.x < 128) g_stats[threadIdx.x] = 0.f;
    if (threadIdx.x < 16)  g_pk[(size_t)NP*16 + threadIdx.x] = 0u;   // zero sentinel row
}

// ============ idx transpose: (n,k) row-major + mask -> k-major folded ============
// int4-vectorized loads (4 j-elements per LDG.128); last partial block takes scalar path.
__global__ void prep_fidx(const int* __restrict__ nbr, const int* __restrict__ mask,
                          int* __restrict__ fidx)
{
    __shared__ int tmp[KK][BT + 1];
    const int tid = threadIdx.x;
    long long gbase = (long long)blockIdx.x * BT * KK;

    if (blockIdx.x != NT2 - 1){
        // full block: BT*KK = 6912 elements = 1728 int4, guaranteed in range
        const int4* nb4 = (const int4*)(nbr + gbase);
        const int4* mk4 = (const int4*)(mask + gbase);
        #pragma unroll 1
        for (int j4 = tid; j4 < (BT*KK)/4; j4 += BT){
            int4 a = nb4[j4];
            int4 m = mk4[j4];
            int j = 4*j4;
            int nl0 = (j+0) / KK, k0 = (j+0) - nl0*KK;
            int nl1 = (j+1) / KK, k1 = (j+1) - nl1*KK;
            int nl2 = (j+2) / KK, k2 = (j+2) - nl2*KK;
            int nl3 = (j+3) / KK, k3 = (j+3) - nl3*KK;
            tmp[k0][nl0] = m.x ? a.x : NP;
            tmp[k1][nl1] = m.y ? a.y : NP;
            tmp[k2][nl2] = m.z ? a.z : NP;
            tmp[k3][nl3] = m.w ? a.w : NP;
        }
    } else {
        // partial block: scalar with bounds checks
        #pragma unroll 1
        for (int j = tid; j < BT*KK; j += BT){
            long long g = gbase + j;
            int v = NP;
            if (g < (long long)NP*KK && mask[g]) v = nbr[g];
            int nl = j / KK, k = j - nl*KK;
            tmp[k][nl] = v;
        }
    }
    __syncthreads();
    int n = blockIdx.x*BT + tid;
    if (n < NP){
        #pragma unroll 1
        for (int k = 0; k < KK; k++) fidx[(size_t)k*NP + n] = tmp[k][tid];
    }
}

// ============ pack input: fp32 row -> 16 fp16-pair words, permuted word order ============
__global__ void pack_input(const float* __restrict__ src, unsigned* __restrict__ dst,
                           int bn, const float* __restrict__ gam, const float* __restrict__ bet)
{
    long long t = (long long)blockIdx.x*blockDim.x + threadIdx.x;
    if (t >= (long long)NP*16) return;
    int q   = (int)(t & 15);
    long long row = t >> 4;
    int p = (q >> 2) + 4*(q & 3);
    int c = 2*p;
    float2 v = *(const float2*)(src + row*CH + c);
    float x = v.x, y = v.y;
    if (bn){
        float m0 = g_stats[c]   * (1.f/NP), m1 = g_stats[c+1]   * (1.f/NP);
        float q0 = g_stats[32+c]* (1.f/NP), q1 = g_stats[32+c+1]* (1.f/NP);
        float s0 = rsqrtf(q0 - m0*m0 + 1e-5f) * gam[c];
        float s1 = rsqrtf(q1 - m1*m1 + 1e-5f) * gam[c+1];
        x = fmaxf(x*s0 + (bet[c]   - m0*s0), 0.f);
        y = fmaxf(y*s1 + (bet[c+1] - m1*s1), 0.f);
    }
    dst[row*16 + q] = pack_f16(x, y);
}

// ============ conv: fp16 single-term, depth-2 register pipeline (R9 structure) ============
__global__ void __launch_bounds__(TPB,2) conv_mma(
    const unsigned char* __restrict__ pk, const unsigned short* __restrict__ wt,
    const int* __restrict__ fidx, float* __restrict__ out, int stats_off)
{
    extern __shared__ char smem[];
    const unsigned sb = smem_u32(smem);
    const int tid = threadIdx.x, w = tid >> 5, lane = tid & 31;
    const int gq = lane & 3, r_lo = lane >> 2;
    const int rbase = blockIdx.x*TILE + w*32 + r_lo;

    if (tid < 64) ((float*)(smem + SM_ST))[tid] = 0.f;
    // W tiles -> smem (55296B)
    {
        const uint4* s = (const uint4*)wt;
        uint4* d = (uint4*)(smem + SM_W);
        #pragma unroll 1
        for (int i = tid; i < (KK*2048)/16; i += TPB) d[i] = s[i];
    }
    __syncthreads();

    const int k0 = (w*27) >> 3;          // warp k-rotation (8 warps)
    int nrow[4];
    #pragma unroll
    for (int m = 0; m < 4; m++){ int n = rbase + m*8; nrow[m] = (n < NP) ? n : -1; }

    uint4 vh[2][4];
    int irC[4];

    // ---- prologue: issue j=0,1; preload idx for j=2 ----
    #pragma unroll
    for (int j = 0; j < 2; j++){
        int kk = k0 + j; if (kk >= KK) kk -= KK;
        #pragma unroll
        for (int m = 0; m < 4; m++){
            int ir = (nrow[m] >= 0) ? fidx[(size_t)kk*NP + nrow[m]] : NP;
            vh[j][m] = *(const uint4*)(pk + (size_t)ir*64 + gq*16);
        }
    }
    {
        int kk = k0 + 2; if (kk >= KK) kk -= KK;
        #pragma unroll
        for (int m = 0; m < 4; m++)
            irC[m] = (nrow[m] >= 0) ? fidx[(size_t)kk*NP + nrow[m]] : NP;
    }

    float acc[2][4][4];
    #pragma unroll
    for (int a = 0; a < 2; a++)
        #pragma unroll
        for (int b = 0; b < 4; b++)
            #pragma unroll
            for (int c = 0; c < 4; c++) acc[a][b][c] = 0.f;

    #pragma unroll 2
    for (int j = 0; j < KK; j++){
        const int buf = j & 1;
        int kk = k0 + j; if (kk >= KK) kk -= KK;

        // ---- snapshot fragments from arrived buffer ----
        unsigned ah[2][2][4];
        #pragma unroll
        for (int rb = 0; rb < 2; rb++){
            const unsigned* r0 = (const unsigned*)&vh[buf][2*rb];
            const unsigned* r1 = (const unsigned*)&vh[buf][2*rb+1];
            ah[rb][0][0]=r0[0]; ah[rb][0][1]=r1[0]; ah[rb][0][2]=r0[1]; ah[rb][0][3]=r1[1];
            ah[rb][1][0]=r0[2]; ah[rb][1][1]=r1[2]; ah[rb][1][2]=r0[3]; ah[rb][1][3]=r1[3];
        }

        // ---- issue j+2 into freed buffer ----
        if (j + 2 < KK){
            #pragma unroll
            for (int m = 0; m < 4; m++)
                vh[buf][m] = *(const uint4*)(pk + (size_t)irC[m]*64 + gq*16);
        }
        // ---- preload idx for j+3 ----
        if (j + 3 < KK){
            int k3 = k0 + j + 3; if (k3 >= KK) k3 -= KK;
            #pragma unroll
            for (int m = 0; m < 4; m++)
                irC[m] = (nrow[m] >= 0) ? fidx[(size_t)k3*NP + nrow[m]] : NP;
        }

        // ---- B per-nq + 16 mma ----
        const unsigned wk = sb + SM_W + kk*2048;
        #pragma unroll
        for (int nq = 0; nq < 4; nq++){
            unsigned bh[4];
            unsigned sw = ((((unsigned)nq) ^ ((lane>>1)&3)) << 4);
            ldmx4t(bh, wk + lane*64 + sw);
            #pragma unroll
            for (int rb = 0; rb < 2; rb++){
                mma16816h(acc[rb][nq], ah[rb][0], bh + 0);
                mma16816h(acc[rb][nq], ah[rb][1], bh + 2);
            }
        }
    }

    // ---- epilogue: store raw conv output + fused BN stats ----
    float sR[8], qR[8];
    #pragma unroll
    for (int i = 0; i < 8; i++){ sR[i] = 0.f; qR[i] = 0.f; }

    const int C0 = gq * 2;
    #pragma unroll
    for (int rb = 0; rb < 2; rb++){
        #pragma unroll
        for (int nq = 0; nq < 4; nq++){
            float a0 = acc[rb][nq][0], a1 = acc[rb][nq][1];
            float a2 = acc[rb][nq][2], a3 = acc[rb][nq][3];
            int m0 = rbase + rb*16, m1 = m0 + 8;
            int c  = nq*8 + C0;
            if (m0 < NP) *(float2*)(out + (size_t)m0*CH + c) = make_float2(a0, a1);
            if (m1 < NP) *(float2*)(out + (size_t)m1*CH + c) = make_float2(a2, a3);
            sR[nq*2+0] += a0 + a2;  qR[nq*2+0] += a0*a0 + a2*a2;
            sR[nq*2+1] += a1 + a3;  qR[nq*2+1] += a1*a1 + a3*a3;
        }
    }
    #pragma unroll
    for (int i = 0; i < 8; i++){
        #pragma unroll
        for (int off = 4; off < 32; off <<= 1){
            sR[i] += __shfl_xor_sync(0xffffffffu, sR[i], off);
            qR[i] += __shfl_xor_sync(0xffffffffu, qR[i], off);
        }
    }
    if (lane < 4){
        float* st = (float*)(smem + SM_ST);
        #pragma unroll
        for (int nq = 0; nq < 4; nq++){
            atomicAdd(&st[     nq*8 + lane*2    ], sR[nq*2+0]);
            atomicAdd(&st[     nq*8 + lane*2 + 1], sR[nq*2+1]);
            atomicAdd(&st[32 + nq*8 + lane*2    ], qR[nq*2+0]);
            atomicAdd(&st[32 + nq*8 + lane*2 + 1], qR[nq*2+1]);
        }
    }
    __syncthreads();
    if (tid < 64) atomicAdd(&g_stats[stats_off + tid], ((float*)(smem + SM_ST))[tid]);
}

// ---- final BN + residual + ReLU ----
__global__ void bnrelu_kernel(const float4* __restrict__ x, int stats_off,
    const float* __restrict__ gamma, const float* __restrict__ beta,
    const float4* __restrict__ res, float4* __restrict__ out)
{
    long long i = (long long)blockIdx.x*blockDim.x + threadIdx.x;
    if (i >= (long long)NP*CH/4) return;
    int c0 = (int)(i & 7) * 4;
    const float invN = 1.0f / NP;
    float4 v = x[i];
    float4 r4 = res[i];
    float4 o;
#define BN_ONE(comp, c) { \
        float mean = g_stats[stats_off + c0 + c] * invN; \
        float var  = g_stats[stats_off + 32 + c0 + c] * invN - mean*mean; \
        float sc   = rsqrtf(var + 1e-5f) * gamma[c0 + c]; \
        float val  = (v.comp - mean)*sc + beta[c0 + c] + r4.comp; \
        o.comp = fmaxf(val, 0.f); }
    BN_ONE(x, 0) BN_ONE(y, 1) BN_ONE(z, 2) BN_ONE(w, 3)
#undef BN_ONE
    out[i] = o;
}

extern "C" void kernel_launch(void* const* d_in, const int* in_sizes, int n_in,
                              void* d_out, int out_size)
{
    const float* feats  = (const float*)d_in[0];
    const float* W1     = (const float*)d_in[1];
    const float* gamma1 = (const float*)d_in[2];
    const float* beta1  = (const float*)d_in[3];
    const float* W2     = (const float*)d_in[4];
    const float* gamma2 = (const float*)d_in[5];
    const float* beta2  = (const float*)d_in[6];
    const int*   nbr    = (const int*)d_in[7];
    const int*   mask   = (const int*)d_in[8];
    float* out = (float*)d_out;

    float *buf1, *buf2; unsigned short* wt; unsigned* pk; int* fidx;
    cudaGetSymbolAddress((void**)&buf1, g_buf1);
    cudaGetSymbolAddress((void**)&buf2, g_buf2);
    cudaGetSymbolAddress((void**)&wt,   g_wt);
    cudaGetSymbolAddress((void**)&pk,   g_pk);
    cudaGetSymbolAddress((void**)&fidx, g_fidx);

    cudaFuncSetAttribute(conv_mma, cudaFuncAttributeMaxDynamicSharedMemorySize, SM_TOT);

    const long long ne4 = (long long)NP*CH/4;
    const int gridb = (int)((ne4 + 255) / 256);
    const int gridp = (int)(((long long)NP*16 + 255) / 256);

    zero_stats<<<1,128>>>();
    prep_w<<<(2*KK*CH*CH + 255)/256, 256>>>(W1, W2);
    prep_fidx<<<NT2, 256>>>(nbr, mask, fidx);
    // pack feats -> pk; conv1: raw -> buf1, stats@0
    pack_input<<<gridp, 256>>>(feats, pk, 0, (const float*)0, (const float*)0);
    conv_mma<<<NT, TPB, SM_TOT>>>((const unsigned char*)pk, wt, fidx, buf1, 0);
    // h = relu(bn1(buf1)) packed -> pk; conv2: raw -> buf2, stats@64
    pack_input<<<gridp, 256>>>(buf1, pk, 1, gamma1, beta1);
    conv_mma<<<NT, TPB, SM_TOT>>>((const unsigned char*)pk, wt + KK*1024, fidx, buf2, 64);
    // out = relu(BN2(buf2) + feats)
    bnrelu_kernel<<<gridb, 256>>>((const float4*)buf2, 64, gamma2, beta2,
                                  (const float4*)feats, (float4*)out);
}

// round 14
// speedup vs baseline: 1.4240x; 1.0540x over previous
#include <cuda_runtime.h>
#include <cuda_fp16.h>

#define NP   400000
#define CH   32
#define KK   27
#define TPB  256
#define TILE 256
#define NT   ((NP + TILE - 1) / TILE)   // 1563
#define BT   256
#define NT2  ((NP + BT - 1) / BT)

// ---- device scratch (allocation-free rule) ----
__device__ float g_buf2[(size_t)NP*CH];
__device__ float g_stats[128];                   // [0:64) conv1 sum/sumsq, [64:128) conv2
__device__ unsigned short g_wt[2][KK*1024];      // per-k 2KB fp16 W tiles, swizzled
__device__ unsigned g_pk[((size_t)NP+1)*16];     // packed fp16 rows 64B; row NP = zeros
__device__ unsigned g_pkraw[(size_t)NP*16];      // conv1 raw output, packed fp16 (pre-BN)
__device__ int g_fidx[(size_t)KK*NP];            // k-major folded idx (mask applied; NP = inactive)

// ---- conv smem layout (bytes) ----
#define SM_W   0                        // 27*2048 = 55296
#define SM_ST  55296                    // 64 floats
#define SM_TOT (SM_ST + 256)            // 55552 -> 2 CTAs/SM

// ============ helpers ============
__device__ __forceinline__ unsigned smem_u32(const void* p){
    unsigned a; asm("{ .reg .u64 t; cvta.to.shared.u64 t, %1; cvt.u32.u64 %0, t; }"
                    : "=r"(a) : "l"(p));
    return a;
}
__device__ __forceinline__ void ldmx4t(unsigned* r, unsigned addr){
    asm volatile("ldmatrix.sync.aligned.m8n8.x4.trans.shared.b16 {%0,%1,%2,%3}, [%4];"
        : "=r"(r[0]),"=r"(r[1]),"=r"(r[2]),"=r"(r[3]) : "r"(addr));
}
__device__ __forceinline__ void mma16816h(float* d, const unsigned* a, const unsigned* b){
    asm volatile("mma.sync.aligned.m16n8k16.row.col.f32.f16.f16.f32 "
        "{%0,%1,%2,%3}, {%4,%5,%6,%7}, {%8,%9}, {%0,%1,%2,%3};"
        : "+f"(d[0]),"+f"(d[1]),"+f"(d[2]),"+f"(d[3])
        : "r"(a[0]),"r"(a[1]),"r"(a[2]),"r"(a[3]), "r"(b[0]),"r"(b[1]));
}
__device__ __forceinline__ unsigned pack_f16(float x, float y){
    __half2 h = __floats2half2_rn(x, y);
    return *(unsigned*)&h;
}

// ============ W prep: fp32 -> swizzled fp16 tiles (B operand) ============
__global__ void prep_w(const float* __restrict__ W1, const float* __restrict__ W2){
    int idx = blockIdx.x*blockDim.x + threadIdx.x;
    if (idx >= 2*KK*CH*CH) return;
    int w   = idx / (KK*CH*CH);
    int rem = idx % (KK*CH*CH);
    int k = rem / (CH*CH);
    int i = (rem / CH) % CH;   // input channel  (GEMM K)  -> row
    int c = rem % CH;          // output channel (GEMM N)  -> col
    float v = (w ? W2 : W1)[(k*CH + i)*CH + c];
    unsigned off = i*64 + ((((unsigned)(c>>3)) ^ ((i>>1)&3)) << 4) + (c&7)*2;
    g_wt[w][k*1024 + (off>>1)] = __half_as_ushort(__float2half_rn(v));
}

__global__ void zero_stats(){
    if (threadIdx.x < 128) g_stats[threadIdx.x] = 0.f;
    if (threadIdx.x < 16)  g_pk[(size_t)NP*16 + threadIdx.x] = 0u;   // zero sentinel row
}

// ============ idx transpose: (n,k) row-major + mask -> k-major folded ============
__global__ void prep_fidx(const int* __restrict__ nbr, const int* __restrict__ mask,
                          int* __restrict__ fidx)
{
    __shared__ int tmp[KK][BT + 1];
    const int tid = threadIdx.x;
    long long gbase = (long long)blockIdx.x * BT * KK;

    if (blockIdx.x != NT2 - 1){
        const int4* nb4 = (const int4*)(nbr + gbase);
        const int4* mk4 = (const int4*)(mask + gbase);
        #pragma unroll 1
        for (int j4 = tid; j4 < (BT*KK)/4; j4 += BT){
            int4 a = __ldcs(&nb4[j4]);
            int4 m = __ldcs(&mk4[j4]);
            int j = 4*j4;
            int nl0 = (j+0) / KK, k0 = (j+0) - nl0*KK;
            int nl1 = (j+1) / KK, k1 = (j+1) - nl1*KK;
            int nl2 = (j+2) / KK, k2 = (j+2) - nl2*KK;
            int nl3 = (j+3) / KK, k3 = (j+3) - nl3*KK;
            tmp[k0][nl0] = m.x ? a.x : NP;
            tmp[k1][nl1] = m.y ? a.y : NP;
            tmp[k2][nl2] = m.z ? a.z : NP;
            tmp[k3][nl3] = m.w ? a.w : NP;
        }
    } else {
        #pragma unroll 1
        for (int j = tid; j < BT*KK; j += BT){
            long long g = gbase + j;
            int v = NP;
            if (g < (long long)NP*KK && mask[g]) v = nbr[g];
            int nl = j / KK, k = j - nl*KK;
            tmp[k][nl] = v;
        }
    }
    __syncthreads();
    int n = blockIdx.x*BT + tid;
    if (n < NP){
        #pragma unroll 1
        for (int k = 0; k < KK; k++) __stcs(&fidx[(size_t)k*NP + n], tmp[k][tid]);
    }
}

// ============ pack input (feats, no BN): fp32 row -> 16 fp16-pair words ============
// word q (0..15) holds channel pair p = (q>>2) + 4*(q&3)
__global__ void pack_input(const float* __restrict__ src, unsigned* __restrict__ dst)
{
    long long t = (long long)blockIdx.x*blockDim.x + threadIdx.x;
    if (t >= (long long)NP*16) return;
    int q   = (int)(t & 15);
    long long row = t >> 4;
    int p = (q >> 2) + 4*(q & 3);
    float2 v = *(const float2*)(src + row*CH + 2*p);
    dst[row*16 + q] = pack_f16(v.x, v.y);
}

// ============ pack_bn: pkraw (fp16, permuted) -> BN1+ReLU -> pk (fp16, permuted) ======
// One uint4 (4 words) per thread; word i of group g covers channel pair c = 2g + 8i.
__global__ void pack_bn(const uint4* __restrict__ raw, uint4* __restrict__ dst,
                        const float* __restrict__ gam, const float* __restrict__ bet)
{
    long long t = (long long)blockIdx.x*blockDim.x + threadIdx.x;
    if (t >= (long long)NP*4) return;
    const int g = (int)(t & 3);
    const float invN = 1.0f / NP;
    float sc[8], sh[8];
    #pragma unroll
    for (int i = 0; i < 4; i++){
        #pragma unroll
        for (int u = 0; u < 2; u++){
            int c = 2*g + 8*i + u;
            float m = g_stats[c] * invN;
            float vv = g_stats[32+c] * invN - m*m;
            float s = rsqrtf(vv + 1e-5f) * gam[c];
            sc[2*i+u] = s;
            sh[2*i+u] = bet[c] - m*s;
        }
    }
    uint4 r = __ldcs(&raw[t]);
    unsigned wv[4] = {r.x, r.y, r.z, r.w};
    #pragma unroll
    for (int i = 0; i < 4; i++){
        __half2 h = *(__half2*)&wv[i];
        float2 f = __half22float2(h);
        float x = fmaxf(f.x*sc[2*i]   + sh[2*i],   0.f);
        float y = fmaxf(f.y*sc[2*i+1] + sh[2*i+1], 0.f);
        wv[i] = pack_f16(x, y);
    }
    dst[t] = make_uint4(wv[0], wv[1], wv[2], wv[3]);
}

// ============ conv: fp16 single-term, depth-2 pipeline; fp16 or fp32 output ============
__global__ void __launch_bounds__(TPB,2) conv_mma(
    const unsigned char* __restrict__ pk, const unsigned short* __restrict__ wt,
    const int* __restrict__ fidx,
    float* __restrict__ outf, unsigned* __restrict__ outh, int stats_off)
{
    extern __shared__ char smem[];
    const unsigned sb = smem_u32(smem);
    const int tid = threadIdx.x, w = tid >> 5, lane = tid & 31;
    const int gq = lane & 3, r_lo = lane >> 2;
    const int rbase = blockIdx.x*TILE + w*32 + r_lo;

    if (tid < 64) ((float*)(smem + SM_ST))[tid] = 0.f;
    // W tiles -> smem (55296B)
    {
        const uint4* s = (const uint4*)wt;
        uint4* d = (uint4*)(smem + SM_W);
        #pragma unroll 1
        for (int i = tid; i < (KK*2048)/16; i += TPB) d[i] = s[i];
    }
    __syncthreads();

    const int k0 = (w*27) >> 3;          // warp k-rotation (8 warps)
    int nrow[4];
    #pragma unroll
    for (int m = 0; m < 4; m++){ int n = rbase + m*8; nrow[m] = (n < NP) ? n : -1; }

    uint4 vh[2][4];
    int irC[4];

    // ---- prologue: issue j=0,1; preload idx for j=2 ----
    #pragma unroll
    for (int j = 0; j < 2; j++){
        int kk = k0 + j; if (kk >= KK) kk -= KK;
        #pragma unroll
        for (int m = 0; m < 4; m++){
            int ir = (nrow[m] >= 0) ? __ldcs(&fidx[(size_t)kk*NP + nrow[m]]) : NP;
            vh[j][m] = *(const uint4*)(pk + (size_t)ir*64 + gq*16);
        }
    }
    {
        int kk = k0 + 2; if (kk >= KK) kk -= KK;
        #pragma unroll
        for (int m = 0; m < 4; m++)
            irC[m] = (nrow[m] >= 0) ? __ldcs(&fidx[(size_t)kk*NP + nrow[m]]) : NP;
    }

    float acc[2][4][4];
    #pragma unroll
    for (int a = 0; a < 2; a++)
        #pragma unroll
        for (int b = 0; b < 4; b++)
            #pragma unroll
            for (int c = 0; c < 4; c++) acc[a][b][c] = 0.f;

    #pragma unroll 2
    for (int j = 0; j < KK; j++){
        const int buf = j & 1;
        int kk = k0 + j; if (kk >= KK) kk -= KK;

        // ---- snapshot fragments from arrived buffer ----
        unsigned ah[2][2][4];
        #pragma unroll
        for (int rb = 0; rb < 2; rb++){
            const unsigned* r0 = (const unsigned*)&vh[buf][2*rb];
            const unsigned* r1 = (const unsigned*)&vh[buf][2*rb+1];
            ah[rb][0][0]=r0[0]; ah[rb][0][1]=r1[0]; ah[rb][0][2]=r0[1]; ah[rb][0][3]=r1[1];
            ah[rb][1][0]=r0[2]; ah[rb][1][1]=r1[2]; ah[rb][1][2]=r0[3]; ah[rb][1][3]=r1[3];
        }

        // ---- issue j+2 into freed buffer ----
        if (j + 2 < KK){
            #pragma unroll
            for (int m = 0; m < 4; m++)
                vh[buf][m] = *(const uint4*)(pk + (size_t)irC[m]*64 + gq*16);
        }
        // ---- preload idx for j+3 ----
        if (j + 3 < KK){
            int k3 = k0 + j + 3; if (k3 >= KK) k3 -= KK;
            #pragma unroll
            for (int m = 0; m < 4; m++)
                irC[m] = (nrow[m] >= 0) ? __ldcs(&fidx[(size_t)k3*NP + nrow[m]]) : NP;
        }

        // ---- B per-nq + 16 mma ----
        const unsigned wk = sb + SM_W + kk*2048;
        #pragma unroll
        for (int nq = 0; nq < 4; nq++){
            unsigned bh[4];
            unsigned sw = ((((unsigned)nq) ^ ((lane>>1)&3)) << 4);
            ldmx4t(bh, wk + lane*64 + sw);
            #pragma unroll
            for (int rb = 0; rb < 2; rb++){
                mma16816h(acc[rb][nq], ah[rb][0], bh + 0);
                mma16816h(acc[rb][nq], ah[rb][1], bh + 2);
            }
        }
    }

    // ---- epilogue: fused BN stats + store (fp16 packed or fp32) ----
    float sR[8], qR[8];
    #pragma unroll
    for (int i = 0; i < 8; i++){ sR[i] = 0.f; qR[i] = 0.f; }

    const int C0 = gq * 2;
    #pragma unroll
    for (int rb = 0; rb < 2; rb++){
        #pragma unroll
        for (int nq = 0; nq < 4; nq++){
            float a0 = acc[rb][nq][0], a1 = acc[rb][nq][1];
            float a2 = acc[rb][nq][2], a3 = acc[rb][nq][3];
            sR[nq*2+0] += a0 + a2;  qR[nq*2+0] += a0*a0 + a2*a2;
            sR[nq*2+1] += a1 + a3;  qR[nq*2+1] += a1*a1 + a3*a3;
        }
    }
    if (outh){
        // packed fp16 output: words q = gq*4 + nq form one uint4 at byte gq*16
        #pragma unroll
        for (int rb = 0; rb < 2; rb++){
            int m0 = rbase + rb*16, m1 = m0 + 8;
            uint4 w0, w1;
            w0.x = pack_f16(acc[rb][0][0], acc[rb][0][1]);
            w0.y = pack_f16(acc[rb][1][0], acc[rb][1][1]);
            w0.z = pack_f16(acc[rb][2][0], acc[rb][2][1]);
            w0.w = pack_f16(acc[rb][3][0], acc[rb][3][1]);
            w1.x = pack_f16(acc[rb][0][2], acc[rb][0][3]);
            w1.y = pack_f16(acc[rb][1][2], acc[rb][1][3]);
            w1.z = pack_f16(acc[rb][2][2], acc[rb][2][3]);
            w1.w = pack_f16(acc[rb][3][2], acc[rb][3][3]);
            if (m0 < NP) __stcs((uint4*)(outh + (size_t)m0*16) + gq, w0);
            if (m1 < NP) __stcs((uint4*)(outh + (size_t)m1*16) + gq, w1);
        }
    } else {
        #pragma unroll
        for (int rb = 0; rb < 2; rb++){
            #pragma unroll
            for (int nq = 0; nq < 4; nq++){
                int m0 = rbase + rb*16, m1 = m0 + 8;
                int c  = nq*8 + C0;
                float2 v0 = make_float2(acc[rb][nq][0], acc[rb][nq][1]);
                float2 v1 = make_float2(acc[rb][nq][2], acc[rb][nq][3]);
                if (m0 < NP) __stcs((float2*)(outf + (size_t)m0*CH + c), v0);
                if (m1 < NP) __stcs((float2*)(outf + (size_t)m1*CH + c), v1);
            }
        }
    }
    #pragma unroll
    for (int i = 0; i < 8; i++){
        #pragma unroll
        for (int off = 4; off < 32; off <<= 1){
            sR[i] += __shfl_xor_sync(0xffffffffu, sR[i], off);
            qR[i] += __shfl_xor_sync(0xffffffffu, qR[i], off);
        }
    }
    if (lane < 4){
        float* st = (float*)(smem + SM_ST);
        #pragma unroll
        for (int nq = 0; nq < 4; nq++){
            atomicAdd(&st[     nq*8 + lane*2    ], sR[nq*2+0]);
            atomicAdd(&st[     nq*8 + lane*2 + 1], sR[nq*2+1]);
            atomicAdd(&st[32 + nq*8 + lane*2    ], qR[nq*2+0]);
            atomicAdd(&st[32 + nq*8 + lane*2 + 1], qR[nq*2+1]);
        }
    }
    __syncthreads();
    if (tid < 64) atomicAdd(&g_stats[stats_off + tid], ((float*)(smem + SM_ST))[tid]);
}

// ---- final BN + residual + ReLU ----
__global__ void bnrelu_kernel(const float4* __restrict__ x, int stats_off,
    const float* __restrict__ gamma, const float* __restrict__ beta,
    const float4* __restrict__ res, float4* __restrict__ out)
{
    long long i = (long long)blockIdx.x*blockDim.x + threadIdx.x;
    if (i >= (long long)NP*CH/4) return;
    int c0 = (int)(i & 7) * 4;
    const float invN = 1.0f / NP;
    float4 v = __ldcs(&x[i]);
    float4 r4 = __ldcs(&res[i]);
    float4 o;
#define BN_ONE(comp, c) { \
        float mean = g_stats[stats_off + c0 + c] * invN; \
        float var  = g_stats[stats_off + 32 + c0 + c] * invN - mean*mean; \
        float sc   = rsqrtf(var + 1e-5f) * gamma[c0 + c]; \
        float val  = (v.comp - mean)*sc + beta[c0 + c] + r4.comp; \
        o.comp = fmaxf(val, 0.f); }
    BN_ONE(x, 0) BN_ONE(y, 1) BN_ONE(z, 2) BN_ONE(w, 3)
#undef BN_ONE
    __stcs(&out[i], o);
}

extern "C" void kernel_launch(void* const* d_in, const int* in_sizes, int n_in,
                              void* d_out, int out_size)
{
    const float* feats  = (const float*)d_in[0];
    const float* W1     = (const float*)d_in[1];
    const float* gamma1 = (const float*)d_in[2];
    const float* beta1  = (const float*)d_in[3];
    const float* W2     = (const float*)d_in[4];
    const float* gamma2 = (const float*)d_in[5];
    const float* beta2  = (const float*)d_in[6];
    const int*   nbr    = (const int*)d_in[7];
    const int*   mask   = (const int*)d_in[8];
    float* out = (float*)d_out;

    float *buf2; unsigned short* wt; unsigned *pk, *pkraw; int* fidx;
    cudaGetSymbolAddress((void**)&buf2,  g_buf2);
    cudaGetSymbolAddress((void**)&wt,    g_wt);
    cudaGetSymbolAddress((void**)&pk,    g_pk);
    cudaGetSymbolAddress((void**)&pkraw, g_pkraw);
    cudaGetSymbolAddress((void**)&fidx,  g_fidx);

    cudaFuncSetAttribute(conv_mma, cudaFuncAttributeMaxDynamicSharedMemorySize, SM_TOT);

    const long long ne4 = (long long)NP*CH/4;
    const int gridb = (int)((ne4 + 255) / 256);
    const int gridp = (int)(((long long)NP*16 + 255) / 256);
    const int gridq = (int)(((long long)NP*4  + 255) / 256);

    zero_stats<<<1,128>>>();
    prep_w<<<(2*KK*CH*CH + 255)/256, 256>>>(W1, W2);
    prep_fidx<<<NT2, 256>>>(nbr, mask, fidx);
    // pack feats -> pk; conv1: packed fp16 raw -> pkraw, stats@0
    pack_input<<<gridp, 256>>>(feats, pk);
    conv_mma<<<NT, TPB, SM_TOT>>>((const unsigned char*)pk, wt, fidx,
                                  (float*)0, pkraw, 0);
    // BN1+ReLU on packed words -> pk; conv2: fp32 raw -> buf2, stats@64
    pack_bn<<<gridq, 256>>>((const uint4*)pkraw, (uint4*)pk, gamma1, beta1);
    conv_mma<<<NT, TPB, SM_TOT>>>((const unsigned char*)pk, wt + KK*1024, fidx,
                                  buf2, (unsigned*)0, 64);
    // out = relu(BN2(buf2) + feats)
    bnrelu_kernel<<<gridb, 256>>>((const float4*)buf2, 64, gamma2, beta2,
                                  (const float4*)feats, (float4*)out);
}

// round 15
// speedup vs baseline: 1.4446x; 1.0145x over previous
#include <cuda_runtime.h>
#include <cuda_fp16.h>

#define NP    400000
#define CH    32
#define KK    27
#define TPB   256
#define TILE  256
#define NT    ((NP + TILE - 1) / TILE)   // 1563
#define BT    256
#define NT2   ((NP + BT - 1) / BT)       // 1563
#define NPAD  (NT*TILE)                  // 400128
#define NPAD4 (NPAD/4)                   // 100032

// ---- device scratch (allocation-free rule) ----
__device__ float g_stats[128];                   // [0:64) conv1 sum/sumsq, [64:128) conv2
__device__ unsigned short g_wt[2][KK*1024];      // per-k 2KB fp16 W tiles, swizzled
__device__ unsigned g_pk[((size_t)NP+1)*16];     // packed fp16 rows 64B; row NP = zeros
__device__ unsigned g_pkraw[(size_t)NP*16];      // conv raw output, packed fp16 (pre-BN)
__device__ int4 g_fidx4[(size_t)KK*NPAD4];       // warp-tile int4 idx: {r, r+8, r+16, r+24}

// ---- conv smem layout (bytes) ----
#define SM_W   0                        // 27*2048 = 55296
#define SM_ST  55296                    // 64 floats
#define SM_TOT (SM_ST + 256)            // 55552 -> 2 CTAs/SM

// ============ helpers ============
__device__ __forceinline__ unsigned smem_u32(const void* p){
    unsigned a; asm("{ .reg .u64 t; cvta.to.shared.u64 t, %1; cvt.u32.u64 %0, t; }"
                    : "=r"(a) : "l"(p));
    return a;
}
__device__ __forceinline__ void ldmx4t(unsigned* r, unsigned addr){
    asm volatile("ldmatrix.sync.aligned.m8n8.x4.trans.shared.b16 {%0,%1,%2,%3}, [%4];"
        : "=r"(r[0]),"=r"(r[1]),"=r"(r[2]),"=r"(r[3]) : "r"(addr));
}
__device__ __forceinline__ void mma16816h(float* d, const unsigned* a, const unsigned* b){
    asm volatile("mma.sync.aligned.m16n8k16.row.col.f32.f16.f16.f32 "
        "{%0,%1,%2,%3}, {%4,%5,%6,%7}, {%8,%9}, {%0,%1,%2,%3};"
        : "+f"(d[0]),"+f"(d[1]),"+f"(d[2]),"+f"(d[3])
        : "r"(a[0]),"r"(a[1]),"r"(a[2]),"r"(a[3]), "r"(b[0]),"r"(b[1]));
}
__device__ __forceinline__ unsigned pack_f16(float x, float y){
    __half2 h = __floats2half2_rn(x, y);
    return *(unsigned*)&h;
}

// ============ W prep: fp32 -> swizzled fp16 tiles (B operand) ============
__global__ void prep_w(const float* __restrict__ W1, const float* __restrict__ W2){
    int idx = blockIdx.x*blockDim.x + threadIdx.x;
    if (idx >= 2*KK*CH*CH) return;
    int w   = idx / (KK*CH*CH);
    int rem = idx % (KK*CH*CH);
    int k = rem / (CH*CH);
    int i = (rem / CH) % CH;   // input channel  (GEMM K)  -> row
    int c = rem % CH;          // output channel (GEMM N)  -> col
    float v = (w ? W2 : W1)[(k*CH + i)*CH + c];
    unsigned off = i*64 + ((((unsigned)(c>>3)) ^ ((i>>1)&3)) << 4) + (c&7)*2;
    g_wt[w][k*1024 + (off>>1)] = __half_as_ushort(__float2half_rn(v));
}

__global__ void zero_stats(){
    if (threadIdx.x < 128) g_stats[threadIdx.x] = 0.f;
    if (threadIdx.x < 16)  g_pk[(size_t)NP*16 + threadIdx.x] = 0u;   // zero sentinel row
}

// ============ idx transpose -> warp-tile int4 layout ============
// fidx4[k*NPAD4 + blk*64 + wg*8 + r_lo] = {idx(B+r_lo), idx(B+r_lo+8), +16, +24},
// B = blk*256 + wg*32. Masked/out-of-range rows -> NP sentinel.
__global__ void prep_fidx(const int* __restrict__ nbr, const int* __restrict__ mask,
                          int4* __restrict__ fidx4)
{
    __shared__ int tmp[KK][BT + 1];
    const int tid = threadIdx.x;
    long long gbase = (long long)blockIdx.x * BT * KK;

    if (blockIdx.x != NT2 - 1){
        const int4* nb4 = (const int4*)(nbr + gbase);
        const int4* mk4 = (const int4*)(mask + gbase);
        #pragma unroll 1
        for (int j4 = tid; j4 < (BT*KK)/4; j4 += BT){
            int4 a = __ldcs(&nb4[j4]);
            int4 m = __ldcs(&mk4[j4]);
            int j = 4*j4;
            int nl0 = (j+0) / KK, k0 = (j+0) - nl0*KK;
            int nl1 = (j+1) / KK, k1 = (j+1) - nl1*KK;
            int nl2 = (j+2) / KK, k2 = (j+2) - nl2*KK;
            int nl3 = (j+3) / KK, k3 = (j+3) - nl3*KK;
            tmp[k0][nl0] = m.x ? a.x : NP;
            tmp[k1][nl1] = m.y ? a.y : NP;
            tmp[k2][nl2] = m.z ? a.z : NP;
            tmp[k3][nl3] = m.w ? a.w : NP;
        }
    } else {
        #pragma unroll 1
        for (int j = tid; j < BT*KK; j += BT){
            long long g = gbase + j;
            int v = NP;
            if (g < (long long)NP*KK && mask[g]) v = nbr[g];
            int nl = j / KK, k = j - nl*KK;
            tmp[k][nl] = v;
        }
    }
    __syncthreads();
    // write phase: 64 int4 per k (per block of 256 rows)
    #pragma unroll 1
    for (int t = tid; t < KK*64; t += BT){
        int k = t >> 6, g = t & 63;
        int wg = g >> 3, rl = g & 7;
        int base = wg*32 + rl;
        int4 v = make_int4(tmp[k][base], tmp[k][base+8], tmp[k][base+16], tmp[k][base+24]);
        __stcs(&fidx4[(size_t)k*NPAD4 + blockIdx.x*64 + g], v);
    }
}

// ============ pack input (feats, no BN): fp32 row -> 16 fp16-pair words ============
// word q (0..15) holds channel pair p = (q>>2) + 4*(q&3)
__global__ void pack_input(const float* __restrict__ src, unsigned* __restrict__ dst)
{
    long long t = (long long)blockIdx.x*blockDim.x + threadIdx.x;
    if (t >= (long long)NP*16) return;
    int q   = (int)(t & 15);
    long long row = t >> 4;
    int p = (q >> 2) + 4*(q & 3);
    float2 v = *(const float2*)(src + row*CH + 2*p);
    dst[row*16 + q] = pack_f16(v.x, v.y);
}

// ============ pack_bn: pkraw (fp16, permuted) -> BN1+ReLU -> pk (fp16, permuted) ======
__global__ void pack_bn(const uint4* __restrict__ raw, uint4* __restrict__ dst,
                        const float* __restrict__ gam, const float* __restrict__ bet)
{
    long long t = (long long)blockIdx.x*blockDim.x + threadIdx.x;
    if (t >= (long long)NP*4) return;
    const int g = (int)(t & 3);
    const float invN = 1.0f / NP;
    float sc[8], sh[8];
    #pragma unroll
    for (int i = 0; i < 4; i++){
        #pragma unroll
        for (int u = 0; u < 2; u++){
            int c = 2*g + 8*i + u;
            float m = g_stats[c] * invN;
            float vv = g_stats[32+c] * invN - m*m;
            float s = rsqrtf(vv + 1e-5f) * gam[c];
            sc[2*i+u] = s;
            sh[2*i+u] = bet[c] - m*s;
        }
    }
    uint4 r = __ldcs(&raw[t]);
    unsigned wv[4] = {r.x, r.y, r.z, r.w};
    #pragma unroll
    for (int i = 0; i < 4; i++){
        __half2 h = *(__half2*)&wv[i];
        float2 f = __half22float2(h);
        float x = fmaxf(f.x*sc[2*i]   + sh[2*i],   0.f);
        float y = fmaxf(f.y*sc[2*i+1] + sh[2*i+1], 0.f);
        wv[i] = pack_f16(x, y);
    }
    dst[t] = make_uint4(wv[0], wv[1], wv[2], wv[3]);
}

// ============ conv: fp16 single-term, depth-2 pipeline, int4 idx loads ============
__global__ void __launch_bounds__(TPB,2) conv_mma(
    const unsigned char* __restrict__ pk, const unsigned short* __restrict__ wt,
    const int4* __restrict__ fidx4, unsigned* __restrict__ outh, int stats_off)
{
    extern __shared__ char smem[];
    const unsigned sb = smem_u32(smem);
    const int tid = threadIdx.x, w = tid >> 5, lane = tid & 31;
    const int gq = lane & 3, r_lo = lane >> 2;
    const int rbase = blockIdx.x*TILE + w*32 + r_lo;
    const size_t b64 = (size_t)blockIdx.x*64 + w*8 + r_lo;

    if (tid < 64) ((float*)(smem + SM_ST))[tid] = 0.f;
    // W tiles -> smem (55296B)
    {
        const uint4* s = (const uint4*)wt;
        uint4* d = (uint4*)(smem + SM_W);
        #pragma unroll 1
        for (int i = tid; i < (KK*2048)/16; i += TPB) d[i] = s[i];
    }
    __syncthreads();

    const int k0 = (w*27) >> 3;          // warp k-rotation (8 warps)

    uint4 vh[2][4];
    int4 iC;

    // ---- prologue: issue j=0,1; preload idx for j=2 ----
    #pragma unroll
    for (int j = 0; j < 2; j++){
        int kk = k0 + j; if (kk >= KK) kk -= KK;
        int4 i4 = __ldcs(&fidx4[(size_t)kk*NPAD4 + b64]);
        vh[j][0] = *(const uint4*)(pk + (size_t)i4.x*64 + gq*16);
        vh[j][1] = *(const uint4*)(pk + (size_t)i4.y*64 + gq*16);
        vh[j][2] = *(const uint4*)(pk + (size_t)i4.z*64 + gq*16);
        vh[j][3] = *(const uint4*)(pk + (size_t)i4.w*64 + gq*16);
    }
    {
        int kk = k0 + 2; if (kk >= KK) kk -= KK;
        iC = __ldcs(&fidx4[(size_t)kk*NPAD4 + b64]);
    }

    float acc[2][4][4];
    #pragma unroll
    for (int a = 0; a < 2; a++)
        #pragma unroll
        for (int b = 0; b < 4; b++)
            #pragma unroll
            for (int c = 0; c < 4; c++) acc[a][b][c] = 0.f;

    #pragma unroll 2
    for (int j = 0; j < KK; j++){
        const int buf = j & 1;
        int kk = k0 + j; if (kk >= KK) kk -= KK;

        // ---- snapshot fragments from arrived buffer ----
        unsigned ah[2][2][4];
        #pragma unroll
        for (int rb = 0; rb < 2; rb++){
            const unsigned* r0 = (const unsigned*)&vh[buf][2*rb];
            const unsigned* r1 = (const unsigned*)&vh[buf][2*rb+1];
            ah[rb][0][0]=r0[0]; ah[rb][0][1]=r1[0]; ah[rb][0][2]=r0[1]; ah[rb][0][3]=r1[1];
            ah[rb][1][0]=r0[2]; ah[rb][1][1]=r1[2]; ah[rb][1][2]=r0[3]; ah[rb][1][3]=r1[3];
        }

        // ---- issue j+2 into freed buffer ----
        if (j + 2 < KK){
            vh[buf][0] = *(const uint4*)(pk + (size_t)iC.x*64 + gq*16);
            vh[buf][1] = *(const uint4*)(pk + (size_t)iC.y*64 + gq*16);
            vh[buf][2] = *(const uint4*)(pk + (size_t)iC.z*64 + gq*16);
            vh[buf][3] = *(const uint4*)(pk + (size_t)iC.w*64 + gq*16);
        }
        // ---- preload idx for j+3 ----
        if (j + 3 < KK){
            int k3 = k0 + j + 3; if (k3 >= KK) k3 -= KK;
            iC = __ldcs(&fidx4[(size_t)k3*NPAD4 + b64]);
        }

        // ---- B per-nq + 16 mma ----
        const unsigned wk = sb + SM_W + kk*2048;
        #pragma unroll
        for (int nq = 0; nq < 4; nq++){
            unsigned bh[4];
            unsigned sw = ((((unsigned)nq) ^ ((lane>>1)&3)) << 4);
            ldmx4t(bh, wk + lane*64 + sw);
            #pragma unroll
            for (int rb = 0; rb < 2; rb++){
                mma16816h(acc[rb][nq], ah[rb][0], bh + 0);
                mma16816h(acc[rb][nq], ah[rb][1], bh + 2);
            }
        }
    }

    // ---- epilogue: fused BN stats + packed fp16 store ----
    float sR[8], qR[8];
    #pragma unroll
    for (int i = 0; i < 8; i++){ sR[i] = 0.f; qR[i] = 0.f; }

    #pragma unroll
    for (int rb = 0; rb < 2; rb++){
        #pragma unroll
        for (int nq = 0; nq < 4; nq++){
            float a0 = acc[rb][nq][0], a1 = acc[rb][nq][1];
            float a2 = acc[rb][nq][2], a3 = acc[rb][nq][3];
            sR[nq*2+0] += a0 + a2;  qR[nq*2+0] += a0*a0 + a2*a2;
            sR[nq*2+1] += a1 + a3;  qR[nq*2+1] += a1*a1 + a3*a3;
        }
    }
    // packed fp16 output: words q = gq*4 + nq form one uint4 at byte gq*16
    #pragma unroll
    for (int rb = 0; rb < 2; rb++){
        int m0 = rbase + rb*16, m1 = m0 + 8;
        uint4 w0, w1;
        w0.x = pack_f16(acc[rb][0][0], acc[rb][0][1]);
        w0.y = pack_f16(acc[rb][1][0], acc[rb][1][1]);
        w0.z = pack_f16(acc[rb][2][0], acc[rb][2][1]);
        w0.w = pack_f16(acc[rb][3][0], acc[rb][3][1]);
        w1.x = pack_f16(acc[rb][0][2], acc[rb][0][3]);
        w1.y = pack_f16(acc[rb][1][2], acc[rb][1][3]);
        w1.z = pack_f16(acc[rb][2][2], acc[rb][2][3]);
        w1.w = pack_f16(acc[rb][3][2], acc[rb][3][3]);
        if (m0 < NP) __stcs((uint4*)(outh + (size_t)m0*16) + gq, w0);
        if (m1 < NP) __stcs((uint4*)(outh + (size_t)m1*16) + gq, w1);
    }
    #pragma unroll
    for (int i = 0; i < 8; i++){
        #pragma unroll
        for (int off = 4; off < 32; off <<= 1){
            sR[i] += __shfl_xor_sync(0xffffffffu, sR[i], off);
            qR[i] += __shfl_xor_sync(0xffffffffu, qR[i], off);
        }
    }
    if (lane < 4){
        float* st = (float*)(smem + SM_ST);
        #pragma unroll
        for (int nq = 0; nq < 4; nq++){
            atomicAdd(&st[     nq*8 + lane*2    ], sR[nq*2+0]);
            atomicAdd(&st[     nq*8 + lane*2 + 1], sR[nq*2+1]);
            atomicAdd(&st[32 + nq*8 + lane*2    ], qR[nq*2+0]);
            atomicAdd(&st[32 + nq*8 + lane*2 + 1], qR[nq*2+1]);
        }
    }
    __syncthreads();
    if (tid < 64) atomicAdd(&g_stats[stats_off + tid], ((float*)(smem + SM_ST))[tid]);
}

// ---- final: BN2(packed fp16 conv2) + residual(feats fp32) + ReLU -> fp32 out ----
__global__ void bnrelu_kernel(const uint4* __restrict__ xh, int stats_off,
    const float* __restrict__ gamma, const float* __restrict__ beta,
    const float* __restrict__ res, float* __restrict__ out)
{
    long long t = (long long)blockIdx.x*blockDim.x + threadIdx.x;
    if (t >= (long long)NP*4) return;
    const int g = (int)(t & 3);
    long long row = t >> 2;
    const float invN = 1.0f / NP;
    uint4 r = __ldcs(&xh[t]);
    unsigned wv[4] = {r.x, r.y, r.z, r.w};
    #pragma unroll
    for (int i = 0; i < 4; i++){
        int c = 2*g + 8*i;
        float m0 = g_stats[stats_off + c]      * invN;
        float m1 = g_stats[stats_off + c + 1]  * invN;
        float v0 = g_stats[stats_off + 32 + c]     * invN - m0*m0;
        float v1 = g_stats[stats_off + 32 + c + 1] * invN - m1*m1;
        float s0 = rsqrtf(v0 + 1e-5f) * gamma[c];
        float s1 = rsqrtf(v1 + 1e-5f) * gamma[c+1];
        __half2 h = *(__half2*)&wv[i];
        float2 f = __half22float2(h);
        float2 rs = __ldcs((const float2*)(res + row*CH + c));
        float o0 = fmaxf(f.x*s0 + (beta[c]   - m0*s0) + rs.x, 0.f);
        float o1 = fmaxf(f.y*s1 + (beta[c+1] - m1*s1) + rs.y, 0.f);
        __stcs((float2*)(out + row*CH + c), make_float2(o0, o1));
    }
}

extern "C" void kernel_launch(void* const* d_in, const int* in_sizes, int n_in,
                              void* d_out, int out_size)
{
    const float* feats  = (const float*)d_in[0];
    const float* W1     = (const float*)d_in[1];
    const float* gamma1 = (const float*)d_in[2];
    const float* beta1  = (const float*)d_in[3];
    const float* W2     = (const float*)d_in[4];
    const float* gamma2 = (const float*)d_in[5];
    const float* beta2  = (const float*)d_in[6];
    const int*   nbr    = (const int*)d_in[7];
    const int*   mask   = (const int*)d_in[8];
    float* out = (float*)d_out;

    unsigned short* wt; unsigned *pk, *pkraw; int4* fidx4;
    cudaGetSymbolAddress((void**)&wt,    g_wt);
    cudaGetSymbolAddress((void**)&pk,    g_pk);
    cudaGetSymbolAddress((void**)&pkraw, g_pkraw);
    cudaGetSymbolAddress((void**)&fidx4, g_fidx4);

    cudaFuncSetAttribute(conv_mma, cudaFuncAttributeMaxDynamicSharedMemorySize, SM_TOT);

    const int gridp = (int)(((long long)NP*16 + 255) / 256);
    const int gridq = (int)(((long long)NP*4  + 255) / 256);

    zero_stats<<<1,128>>>();
    prep_w<<<(2*KK*CH*CH + 255)/256, 256>>>(W1, W2);
    prep_fidx<<<NT2, 256>>>(nbr, mask, fidx4);
    // pack feats -> pk; conv1: packed fp16 raw -> pkraw, stats@0
    pack_input<<<gridp, 256>>>(feats, pk);
    conv_mma<<<NT, TPB, SM_TOT>>>((const unsigned char*)pk, wt, fidx4, pkraw, 0);
    // BN1+ReLU on packed words -> pk; conv2: packed fp16 raw -> pkraw, stats@64
    pack_bn<<<gridq, 256>>>((const uint4*)pkraw, (uint4*)pk, gamma1, beta1);
    conv_mma<<<NT, TPB, SM_TOT>>>((const unsigned char*)pk, wt + KK*1024, fidx4, pkraw, 64);
    // out = relu(BN2(pkraw) + feats)
    bnrelu_kernel<<<gridq, 256>>>((const uint4*)pkraw, 64, gamma2, beta2,
                                  feats, out);
}

// round 16
// speedup vs baseline: 1.5586x; 1.0790x over previous
#include <cuda_runtime.h>
#include <cuda_fp16.h>

#define NP    400000
#define CH    32
#define KK    27
#define TPB   256
#define TILE  256
#define NT    ((NP + TILE - 1) / TILE)   // 1563
#define BT    256
#define NT2   ((NP + BT - 1) / BT)       // 1563
#define NPAD  (NT*TILE)                  // 400128
#define NPAD4 (NPAD/4)                   // 100032

// ---- device scratch (allocation-free rule) ----
__device__ float g_stats[128];                   // [0:64) conv1 sum/sumsq, [64:128) conv2
__device__ unsigned short g_wt[2][KK*1024];      // per-k 2KB fp16 W tiles, swizzled
__device__ unsigned g_pk[((size_t)NP+1)*16];     // packed fp16 rows 64B; row NP = zeros
__device__ unsigned g_pkraw[(size_t)NP*16];      // conv raw output, packed fp16 (pre-BN)
__device__ int4 g_fidx4[(size_t)KK*NPAD4];       // warp-tile int4 idx: {r, r+8, r+16, r+24}

// ---- conv smem layout (bytes) ----
#define SM_W   0                        // 27*2048 = 55296
#define SM_ST  55296                    // 64 floats
#define SM_TOT (SM_ST + 256)            // 55552 -> 2 CTAs/SM

// ============ helpers ============
__device__ __forceinline__ unsigned smem_u32(const void* p){
    unsigned a; asm("{ .reg .u64 t; cvta.to.shared.u64 t, %1; cvt.u32.u64 %0, t; }"
                    : "=r"(a) : "l"(p));
    return a;
}
__device__ __forceinline__ void ldmx4t(unsigned* r, unsigned addr){
    asm volatile("ldmatrix.sync.aligned.m8n8.x4.trans.shared.b16 {%0,%1,%2,%3}, [%4];"
        : "=r"(r[0]),"=r"(r[1]),"=r"(r[2]),"=r"(r[3]) : "r"(addr));
}
__device__ __forceinline__ void mma16816h(float* d, const unsigned* a, const unsigned* b){
    asm volatile("mma.sync.aligned.m16n8k16.row.col.f32.f16.f16.f32 "
        "{%0,%1,%2,%3}, {%4,%5,%6,%7}, {%8,%9}, {%0,%1,%2,%3};"
        : "+f"(d[0]),"+f"(d[1]),"+f"(d[2]),"+f"(d[3])
        : "r"(a[0]),"r"(a[1]),"r"(a[2]),"r"(a[3]), "r"(b[0]),"r"(b[1]));
}
__device__ __forceinline__ unsigned pack_f16(float x, float y){
    __half2 h = __floats2half2_rn(x, y);
    return *(unsigned*)&h;
}

// ============ W prep: fp32 -> swizzled fp16 tiles (B operand) ============
__global__ void prep_w(const float* __restrict__ W1, const float* __restrict__ W2){
    int idx = blockIdx.x*blockDim.x + threadIdx.x;
    if (idx >= 2*KK*CH*CH) return;
    int w   = idx / (KK*CH*CH);
    int rem = idx % (KK*CH*CH);
    int k = rem / (CH*CH);
    int i = (rem / CH) % CH;   // input channel  (GEMM K)  -> row
    int c = rem % CH;          // output channel (GEMM N)  -> col
    float v = (w ? W2 : W1)[(k*CH + i)*CH + c];
    unsigned off = i*64 + ((((unsigned)(c>>3)) ^ ((i>>1)&3)) << 4) + (c&7)*2;
    g_wt[w][k*1024 + (off>>1)] = __half_as_ushort(__float2half_rn(v));
}

__global__ void zero_stats(){
    if (threadIdx.x < 128) g_stats[threadIdx.x] = 0.f;
    if (threadIdx.x < 16)  g_pk[(size_t)NP*16 + threadIdx.x] = 0u;   // zero sentinel row
}

// ============ idx transpose -> warp-tile int4 layout ============
// fidx4[k*NPAD4 + blk*64 + wg*8 + r_lo] = {idx(B+r_lo), idx(B+r_lo+8), +16, +24},
// B = blk*256 + wg*32. Masked/out-of-range rows -> NP sentinel.
// Output stored DEFAULT (read twice by the convs; must stay L2-resident).
__global__ void prep_fidx(const int* __restrict__ nbr, const int* __restrict__ mask,
                          int4* __restrict__ fidx4)
{
    __shared__ int tmp[KK][BT + 1];
    const int tid = threadIdx.x;
    long long gbase = (long long)blockIdx.x * BT * KK;

    if (blockIdx.x != NT2 - 1){
        const int4* nb4 = (const int4*)(nbr + gbase);
        const int4* mk4 = (const int4*)(mask + gbase);
        #pragma unroll 1
        for (int j4 = tid; j4 < (BT*KK)/4; j4 += BT){
            int4 a = __ldcs(&nb4[j4]);
            int4 m = __ldcs(&mk4[j4]);
            int j = 4*j4;
            int nl0 = (j+0) / KK, k0 = (j+0) - nl0*KK;
            int nl1 = (j+1) / KK, k1 = (j+1) - nl1*KK;
            int nl2 = (j+2) / KK, k2 = (j+2) - nl2*KK;
            int nl3 = (j+3) / KK, k3 = (j+3) - nl3*KK;
            tmp[k0][nl0] = m.x ? a.x : NP;
            tmp[k1][nl1] = m.y ? a.y : NP;
            tmp[k2][nl2] = m.z ? a.z : NP;
            tmp[k3][nl3] = m.w ? a.w : NP;
        }
    } else {
        #pragma unroll 1
        for (int j = tid; j < BT*KK; j += BT){
            long long g = gbase + j;
            int v = NP;
            if (g < (long long)NP*KK && mask[g]) v = nbr[g];
            int nl = j / KK, k = j - nl*KK;
            tmp[k][nl] = v;
        }
    }
    __syncthreads();
    #pragma unroll 1
    for (int t = tid; t < KK*64; t += BT){
        int k = t >> 6, g = t & 63;
        int wg = g >> 3, rl = g & 7;
        int base = wg*32 + rl;
        fidx4[(size_t)k*NPAD4 + blockIdx.x*64 + g] =
            make_int4(tmp[k][base], tmp[k][base+8], tmp[k][base+16], tmp[k][base+24]);
    }
}

// ============ pack input (feats, no BN): one uint4 (4 words) per thread ============
// uint4 group g covers words 4g+i -> channel pairs p = g + 4i -> channels {2g+8i, +1}
__global__ void pack_input(const float* __restrict__ src, uint4* __restrict__ dst)
{
    long long t = (long long)blockIdx.x*blockDim.x + threadIdx.x;
    if (t >= (long long)NP*4) return;
    const int g = (int)(t & 3);
    long long row = t >> 2;
    const float* rp = src + row*CH + 2*g;
    float2 v0 = __ldcs((const float2*)(rp + 0));
    float2 v1 = __ldcs((const float2*)(rp + 8));
    float2 v2 = __ldcs((const float2*)(rp + 16));
    float2 v3 = __ldcs((const float2*)(rp + 24));
    dst[t] = make_uint4(pack_f16(v0.x, v0.y), pack_f16(v1.x, v1.y),
                        pack_f16(v2.x, v2.y), pack_f16(v3.x, v3.y));
}

// ============ pack_bn: pkraw (fp16, permuted) -> BN1+ReLU -> pk (fp16, permuted) ======
__global__ void pack_bn(const uint4* __restrict__ raw, uint4* __restrict__ dst,
                        const float* __restrict__ gam, const float* __restrict__ bet)
{
    long long t = (long long)blockIdx.x*blockDim.x + threadIdx.x;
    if (t >= (long long)NP*4) return;
    const int g = (int)(t & 3);
    const float invN = 1.0f / NP;
    float sc[8], sh[8];
    #pragma unroll
    for (int i = 0; i < 4; i++){
        #pragma unroll
        for (int u = 0; u < 2; u++){
            int c = 2*g + 8*i + u;
            float m = g_stats[c] * invN;
            float vv = g_stats[32+c] * invN - m*m;
            float s = rsqrtf(vv + 1e-5f) * gam[c];
            sc[2*i+u] = s;
            sh[2*i+u] = bet[c] - m*s;
        }
    }
    uint4 r = raw[t];
    unsigned wv[4] = {r.x, r.y, r.z, r.w};
    #pragma unroll
    for (int i = 0; i < 4; i++){
        __half2 h = *(__half2*)&wv[i];
        float2 f = __half22float2(h);
        float x = fmaxf(f.x*sc[2*i]   + sh[2*i],   0.f);
        float y = fmaxf(f.y*sc[2*i+1] + sh[2*i+1], 0.f);
        wv[i] = pack_f16(x, y);
    }
    dst[t] = make_uint4(wv[0], wv[1], wv[2], wv[3]);
}

// ============ conv: fp16 single-term, depth-2 pipeline, int4 idx loads ============
__global__ void __launch_bounds__(TPB,2) conv_mma(
    const unsigned char* __restrict__ pk, const unsigned short* __restrict__ wt,
    const int4* __restrict__ fidx4, unsigned* __restrict__ outh, int stats_off)
{
    extern __shared__ char smem[];
    const unsigned sb = smem_u32(smem);
    const int tid = threadIdx.x, w = tid >> 5, lane = tid & 31;
    const int gq = lane & 3, r_lo = lane >> 2;
    const int rbase = blockIdx.x*TILE + w*32 + r_lo;
    const size_t b64 = (size_t)blockIdx.x*64 + w*8 + r_lo;

    if (tid < 64) ((float*)(smem + SM_ST))[tid] = 0.f;
    // W tiles -> smem (55296B)
    {
        const uint4* s = (const uint4*)wt;
        uint4* d = (uint4*)(smem + SM_W);
        #pragma unroll 1
        for (int i = tid; i < (KK*2048)/16; i += TPB) d[i] = s[i];
    }
    __syncthreads();

    const int k0 = (w*27) >> 3;          // warp k-rotation (8 warps)

    uint4 vh[2][4];
    int4 iC;

    // ---- prologue: issue j=0,1; preload idx for j=2 ----
    #pragma unroll
    for (int j = 0; j < 2; j++){
        int kk = k0 + j; if (kk >= KK) kk -= KK;
        int4 i4 = fidx4[(size_t)kk*NPAD4 + b64];
        vh[j][0] = *(const uint4*)(pk + (size_t)i4.x*64 + gq*16);
        vh[j][1] = *(const uint4*)(pk + (size_t)i4.y*64 + gq*16);
        vh[j][2] = *(const uint4*)(pk + (size_t)i4.z*64 + gq*16);
        vh[j][3] = *(const uint4*)(pk + (size_t)i4.w*64 + gq*16);
    }
    {
        int kk = k0 + 2; if (kk >= KK) kk -= KK;
        iC = fidx4[(size_t)kk*NPAD4 + b64];
    }

    float acc[2][4][4];
    #pragma unroll
    for (int a = 0; a < 2; a++)
        #pragma unroll
        for (int b = 0; b < 4; b++)
            #pragma unroll
            for (int c = 0; c < 4; c++) acc[a][b][c] = 0.f;

    #pragma unroll 2
    for (int j = 0; j < KK; j++){
        const int buf = j & 1;
        int kk = k0 + j; if (kk >= KK) kk -= KK;

        // ---- snapshot fragments from arrived buffer ----
        unsigned ah[2][2][4];
        #pragma unroll
        for (int rb = 0; rb < 2; rb++){
            const unsigned* r0 = (const unsigned*)&vh[buf][2*rb];
            const unsigned* r1 = (const unsigned*)&vh[buf][2*rb+1];
            ah[rb][0][0]=r0[0]; ah[rb][0][1]=r1[0]; ah[rb][0][2]=r0[1]; ah[rb][0][3]=r1[1];
            ah[rb][1][0]=r0[2]; ah[rb][1][1]=r1[2]; ah[rb][1][2]=r0[3]; ah[rb][1][3]=r1[3];
        }

        // ---- issue j+2 into freed buffer ----
        if (j + 2 < KK){
            vh[buf][0] = *(const uint4*)(pk + (size_t)iC.x*64 + gq*16);
            vh[buf][1] = *(const uint4*)(pk + (size_t)iC.y*64 + gq*16);
            vh[buf][2] = *(const uint4*)(pk + (size_t)iC.z*64 + gq*16);
            vh[buf][3] = *(const uint4*)(pk + (size_t)iC.w*64 + gq*16);
        }
        // ---- preload idx for j+3 ----
        if (j + 3 < KK){
            int k3 = k0 + j + 3; if (k3 >= KK) k3 -= KK;
            iC = fidx4[(size_t)k3*NPAD4 + b64];
        }

        // ---- B per-nq + 16 mma ----
        const unsigned wk = sb + SM_W + kk*2048;
        #pragma unroll
        for (int nq = 0; nq < 4; nq++){
            unsigned bh[4];
            unsigned sw = ((((unsigned)nq) ^ ((lane>>1)&3)) << 4);
            ldmx4t(bh, wk + lane*64 + sw);
            #pragma unroll
            for (int rb = 0; rb < 2; rb++){
                mma16816h(acc[rb][nq], ah[rb][0], bh + 0);
                mma16816h(acc[rb][nq], ah[rb][1], bh + 2);
            }
        }
    }

    // ---- epilogue: fused BN stats + packed fp16 store (default: consumed next kernel) ----
    float sR[8], qR[8];
    #pragma unroll
    for (int i = 0; i < 8; i++){ sR[i] = 0.f; qR[i] = 0.f; }

    #pragma unroll
    for (int rb = 0; rb < 2; rb++){
        #pragma unroll
        for (int nq = 0; nq < 4; nq++){
            float a0 = acc[rb][nq][0], a1 = acc[rb][nq][1];
            float a2 = acc[rb][nq][2], a3 = acc[rb][nq][3];
            sR[nq*2+0] += a0 + a2;  qR[nq*2+0] += a0*a0 + a2*a2;
            sR[nq*2+1] += a1 + a3;  qR[nq*2+1] += a1*a1 + a3*a3;
        }
    }
    #pragma unroll
    for (int rb = 0; rb < 2; rb++){
        int m0 = rbase + rb*16, m1 = m0 + 8;
        uint4 w0, w1;
        w0.x = pack_f16(acc[rb][0][0], acc[rb][0][1]);
        w0.y = pack_f16(acc[rb][1][0], acc[rb][1][1]);
        w0.z = pack_f16(acc[rb][2][0], acc[rb][2][1]);
        w0.w = pack_f16(acc[rb][3][0], acc[rb][3][1]);
        w1.x = pack_f16(acc[rb][0][2], acc[rb][0][3]);
        w1.y = pack_f16(acc[rb][1][2], acc[rb][1][3]);
        w1.z = pack_f16(acc[rb][2][2], acc[rb][2][3]);
        w1.w = pack_f16(acc[rb][3][2], acc[rb][3][3]);
        if (m0 < NP) ((uint4*)(outh + (size_t)m0*16))[gq] = w0;
        if (m1 < NP) ((uint4*)(outh + (size_t)m1*16))[gq] = w1;
    }
    #pragma unroll
    for (int i = 0; i < 8; i++){
        #pragma unroll
        for (int off = 4; off < 32; off <<= 1){
            sR[i] += __shfl_xor_sync(0xffffffffu, sR[i], off);
            qR[i] += __shfl_xor_sync(0xffffffffu, qR[i], off);
        }
    }
    if (lane < 4){
        float* st = (float*)(smem + SM_ST);
        #pragma unroll
        for (int nq = 0; nq < 4; nq++){
            atomicAdd(&st[     nq*8 + lane*2    ], sR[nq*2+0]);
            atomicAdd(&st[     nq*8 + lane*2 + 1], sR[nq*2+1]);
            atomicAdd(&st[32 + nq*8 + lane*2    ], qR[nq*2+0]);
            atomicAdd(&st[32 + nq*8 + lane*2 + 1], qR[nq*2+1]);
        }
    }
    __syncthreads();
    if (tid < 64) atomicAdd(&g_stats[stats_off + tid], ((float*)(smem + SM_ST))[tid]);
}

// ---- final: BN2(packed fp16 conv2) + residual(feats fp32) + ReLU -> fp32 out ----
__global__ void bnrelu_kernel(const uint4* __restrict__ xh, int stats_off,
    const float* __restrict__ gamma, const float* __restrict__ beta,
    const float* __restrict__ res, float* __restrict__ out)
{
    long long t = (long long)blockIdx.x*blockDim.x + threadIdx.x;
    if (t >= (long long)NP*4) return;
    const int g = (int)(t & 3);
    long long row = t >> 2;
    const float invN = 1.0f / NP;
    uint4 r = xh[t];
    unsigned wv[4] = {r.x, r.y, r.z, r.w};
    #pragma unroll
    for (int i = 0; i < 4; i++){
        int c = 2*g + 8*i;
        float m0 = g_stats[stats_off + c]      * invN;
        float m1 = g_stats[stats_off + c + 1]  * invN;
        float v0 = g_stats[stats_off + 32 + c]     * invN - m0*m0;
        float v1 = g_stats[stats_off + 32 + c + 1] * invN - m1*m1;
        float s0 = rsqrtf(v0 + 1e-5f) * gamma[c];
        float s1 = rsqrtf(v1 + 1e-5f) * gamma[c+1];
        __half2 h = *(__half2*)&wv[i];
        float2 f = __half22float2(h);
        float2 rs = __ldcs((const float2*)(res + row*CH + c));
        float o0 = fmaxf(f.x*s0 + (beta[c]   - m0*s0) + rs.x, 0.f);
        float o1 = fmaxf(f.y*s1 + (beta[c+1] - m1*s1) + rs.y, 0.f);
        __stcs((float2*)(out + row*CH + c), make_float2(o0, o1));
    }
}

extern "C" void kernel_launch(void* const* d_in, const int* in_sizes, int n_in,
                              void* d_out, int out_size)
{
    const float* feats  = (const float*)d_in[0];
    const float* W1     = (const float*)d_in[1];
    const float* gamma1 = (const float*)d_in[2];
    const float* beta1  = (const float*)d_in[3];
    const float* W2     = (const float*)d_in[4];
    const float* gamma2 = (const float*)d_in[5];
    const float* beta2  = (const float*)d_in[6];
    const int*   nbr    = (const int*)d_in[7];
    const int*   mask   = (const int*)d_in[8];
    float* out = (float*)d_out;

    unsigned short* wt; unsigned *pk, *pkraw; int4* fidx4;
    cudaGetSymbolAddress((void**)&wt,    g_wt);
    cudaGetSymbolAddress((void**)&pk,    g_pk);
    cudaGetSymbolAddress((void**)&pkraw, g_pkraw);
    cudaGetSymbolAddress((void**)&fidx4, g_fidx4);

    cudaFuncSetAttribute(conv_mma, cudaFuncAttributeMaxDynamicSharedMemorySize, SM_TOT);

    const int gridq = (int)(((long long)NP*4 + 255) / 256);

    zero_stats<<<1,128>>>();
    prep_w<<<(2*KK*CH*CH + 255)/256, 256>>>(W1, W2);
    prep_fidx<<<NT2, 256>>>(nbr, mask, fidx4);
    // pack feats -> pk; conv1: packed fp16 raw -> pkraw, stats@0
    pack_input<<<gridq, 256>>>(feats, (uint4*)pk);
    conv_mma<<<NT, TPB, SM_TOT>>>((const unsigned char*)pk, wt, fidx4, pkraw, 0);
    // BN1+ReLU on packed words -> pk; conv2: packed fp16 raw -> pkraw, stats@64
    pack_bn<<<gridq, 256>>>((const uint4*)pkraw, (uint4*)pk, gamma1, beta1);
    conv_mma<<<NT, TPB, SM_TOT>>>((const unsigned char*)pk, wt + KK*1024, fidx4, pkraw, 64);
    // out = relu(BN2(pkraw) + feats)
    bnrelu_kernel<<<gridq, 256>>>((const uint4*)pkraw, 64, gamma2, beta2,
                                  feats, out);
}

// round 17
// speedup vs baseline: 1.5706x; 1.0077x over previous
#include <cuda_runtime.h>
#include <cuda_fp16.h>

#define NP    400000
#define CH    32
#define KK    27
#define TPB   256
#define TILE  256
#define NT    ((NP + TILE - 1) / TILE)   // 1563
#define BT    256
#define NT2   ((NP + BT - 1) / BT)       // 1563
#define NPAD  (NT*TILE)                  // 400128
#define NPAD4 (NPAD/4)                   // 100032

// ---- device scratch (allocation-free rule) ----
__device__ float g_stats[128];                   // [0:64) conv1 sum/sumsq, [64:128) conv2
__device__ unsigned short g_wt[2][KK*1024];      // per-k 2KB fp16 W tiles, swizzled
__device__ unsigned g_pkA[((size_t)NP+1)*16];    // packed fp16 feats; row NP = zeros
__device__ unsigned g_pkB[(size_t)NP*16];        // packed fp16 conv2 input (post-BN1)
__device__ unsigned g_pkraw[(size_t)NP*16];      // conv raw output, packed fp16 (pre-BN)
__device__ int4 g_fidx4[(size_t)KK*NPAD4];       // warp-tile int4 idx: {r, r+8, r+16, r+24}

// ---- conv smem layout (bytes) ----
#define SM_W   0                        // 27*2048 = 55296
#define SM_ST  55296                    // 64 floats
#define SM_TOT (SM_ST + 256)            // 55552 -> 2 CTAs/SM

// ============ helpers ============
__device__ __forceinline__ unsigned smem_u32(const void* p){
    unsigned a; asm("{ .reg .u64 t; cvta.to.shared.u64 t, %1; cvt.u32.u64 %0, t; }"
                    : "=r"(a) : "l"(p));
    return a;
}
__device__ __forceinline__ void ldmx4t(unsigned* r, unsigned addr){
    asm volatile("ldmatrix.sync.aligned.m8n8.x4.trans.shared.b16 {%0,%1,%2,%3}, [%4];"
        : "=r"(r[0]),"=r"(r[1]),"=r"(r[2]),"=r"(r[3]) : "r"(addr));
}
__device__ __forceinline__ void mma16816h(float* d, const unsigned* a, const unsigned* b){
    asm volatile("mma.sync.aligned.m16n8k16.row.col.f32.f16.f16.f32 "
        "{%0,%1,%2,%3}, {%4,%5,%6,%7}, {%8,%9}, {%0,%1,%2,%3};"
        : "+f"(d[0]),"+f"(d[1]),"+f"(d[2]),"+f"(d[3])
        : "r"(a[0]),"r"(a[1]),"r"(a[2]),"r"(a[3]), "r"(b[0]),"r"(b[1]));
}
__device__ __forceinline__ unsigned pack_f16(float x, float y){
    __half2 h = __floats2half2_rn(x, y);
    return *(unsigned*)&h;
}

// ============ W prep (+ stats/sentinel init folded in) ============
__global__ void prep_w(const float* __restrict__ W1, const float* __restrict__ W2){
    int idx = blockIdx.x*blockDim.x + threadIdx.x;
    if (blockIdx.x == 0){
        if (threadIdx.x < 128) g_stats[threadIdx.x] = 0.f;
        if (threadIdx.x >= 128 && threadIdx.x < 144)
            g_pkA[(size_t)NP*16 + (threadIdx.x - 128)] = 0u;   // zero sentinel row
    }
    if (idx >= 2*KK*CH*CH) return;
    int w   = idx / (KK*CH*CH);
    int rem = idx % (KK*CH*CH);
    int k = rem / (CH*CH);
    int i = (rem / CH) % CH;   // input channel  (GEMM K)  -> row
    int c = rem % CH;          // output channel (GEMM N)  -> col
    float v = (w ? W2 : W1)[(k*CH + i)*CH + c];
    unsigned off = i*64 + ((((unsigned)(c>>3)) ^ ((i>>1)&3)) << 4) + (c&7)*2;
    g_wt[w][k*1024 + (off>>1)] = __half_as_ushort(__float2half_rn(v));
}

// ============ idx transpose -> warp-tile int4 layout (default stores; read twice) ====
__global__ void prep_fidx(const int* __restrict__ nbr, const int* __restrict__ mask,
                          int4* __restrict__ fidx4)
{
    __shared__ int tmp[KK][BT + 1];
    const int tid = threadIdx.x;
    long long gbase = (long long)blockIdx.x * BT * KK;

    if (blockIdx.x != NT2 - 1){
        const int4* nb4 = (const int4*)(nbr + gbase);
        const int4* mk4 = (const int4*)(mask + gbase);
        #pragma unroll 1
        for (int j4 = tid; j4 < (BT*KK)/4; j4 += BT){
            int4 a = __ldcs(&nb4[j4]);
            int4 m = __ldcs(&mk4[j4]);
            int j = 4*j4;
            int nl0 = (j+0) / KK, k0 = (j+0) - nl0*KK;
            int nl1 = (j+1) / KK, k1 = (j+1) - nl1*KK;
            int nl2 = (j+2) / KK, k2 = (j+2) - nl2*KK;
            int nl3 = (j+3) / KK, k3 = (j+3) - nl3*KK;
            tmp[k0][nl0] = m.x ? a.x : NP;
            tmp[k1][nl1] = m.y ? a.y : NP;
            tmp[k2][nl2] = m.z ? a.z : NP;
            tmp[k3][nl3] = m.w ? a.w : NP;
        }
    } else {
        #pragma unroll 1
        for (int j = tid; j < BT*KK; j += BT){
            long long g = gbase + j;
            int v = NP;
            if (g < (long long)NP*KK && mask[g]) v = nbr[g];
            int nl = j / KK, k = j - nl*KK;
            tmp[k][nl] = v;
        }
    }
    __syncthreads();
    #pragma unroll 1
    for (int t = tid; t < KK*64; t += BT){
        int k = t >> 6, g = t & 63;
        int wg = g >> 3, rl = g & 7;
        int base = wg*32 + rl;
        fidx4[(size_t)k*NPAD4 + blockIdx.x*64 + g] =
            make_int4(tmp[k][base], tmp[k][base+8], tmp[k][base+16], tmp[k][base+24]);
    }
}

// ============ pack input (feats): one uint4 (4 words) per thread ============
// uint4 group g covers words 4g+i -> channel pairs p = g + 4i -> channels {2g+8i, +1}
__global__ void pack_input(const float* __restrict__ src, uint4* __restrict__ dst)
{
    long long t = (long long)blockIdx.x*blockDim.x + threadIdx.x;
    if (t >= (long long)NP*4) return;
    const int g = (int)(t & 3);
    long long row = t >> 2;
    const float* rp = src + row*CH + 2*g;
    float2 v0 = __ldcs((const float2*)(rp + 0));
    float2 v1 = __ldcs((const float2*)(rp + 8));
    float2 v2 = __ldcs((const float2*)(rp + 16));
    float2 v3 = __ldcs((const float2*)(rp + 24));
    dst[t] = make_uint4(pack_f16(v0.x, v0.y), pack_f16(v1.x, v1.y),
                        pack_f16(v2.x, v2.y), pack_f16(v3.x, v3.y));
}

// ============ pack_bn: pkraw (fp16, permuted) -> BN1+ReLU -> pkB ============
__global__ void pack_bn(const uint4* __restrict__ raw, uint4* __restrict__ dst,
                        const float* __restrict__ gam, const float* __restrict__ bet)
{
    long long t = (long long)blockIdx.x*blockDim.x + threadIdx.x;
    if (t >= (long long)NP*4) return;
    const int g = (int)(t & 3);
    const float invN = 1.0f / NP;
    float sc[8], sh[8];
    #pragma unroll
    for (int i = 0; i < 4; i++){
        #pragma unroll
        for (int u = 0; u < 2; u++){
            int c = 2*g + 8*i + u;
            float m = g_stats[c] * invN;
            float vv = g_stats[32+c] * invN - m*m;
            float s = rsqrtf(vv + 1e-5f) * gam[c];
            sc[2*i+u] = s;
            sh[2*i+u] = bet[c] - m*s;
        }
    }
    uint4 r = raw[t];
    unsigned wv[4] = {r.x, r.y, r.z, r.w};
    #pragma unroll
    for (int i = 0; i < 4; i++){
        __half2 h = *(__half2*)&wv[i];
        float2 f = __half22float2(h);
        float x = fmaxf(f.x*sc[2*i]   + sh[2*i],   0.f);
        float y = fmaxf(f.y*sc[2*i+1] + sh[2*i+1], 0.f);
        wv[i] = pack_f16(x, y);
    }
    dst[t] = make_uint4(wv[0], wv[1], wv[2], wv[3]);
}

// ============ conv: fp16 single-term, depth-2 pipeline, int4 idx loads ============
__global__ void __launch_bounds__(TPB,2) conv_mma(
    const unsigned char* __restrict__ pk, const unsigned short* __restrict__ wt,
    const int4* __restrict__ fidx4, unsigned* __restrict__ outh, int stats_off)
{
    extern __shared__ char smem[];
    const unsigned sb = smem_u32(smem);
    const int tid = threadIdx.x, w = tid >> 5, lane = tid & 31;
    const int gq = lane & 3, r_lo = lane >> 2;
    const int rbase = blockIdx.x*TILE + w*32 + r_lo;
    const size_t b64 = (size_t)blockIdx.x*64 + w*8 + r_lo;

    if (tid < 64) ((float*)(smem + SM_ST))[tid] = 0.f;
    // W tiles -> smem (55296B)
    {
        const uint4* s = (const uint4*)wt;
        uint4* d = (uint4*)(smem + SM_W);
        #pragma unroll 1
        for (int i = tid; i < (KK*2048)/16; i += TPB) d[i] = s[i];
    }
    __syncthreads();

    const int k0 = (w*27) >> 3;          // warp k-rotation (8 warps)

    uint4 vh[2][4];
    int4 iC;

    // ---- prologue: issue j=0,1; preload idx for j=2 ----
    #pragma unroll
    for (int j = 0; j < 2; j++){
        int kk = k0 + j; if (kk >= KK) kk -= KK;
        int4 i4 = fidx4[(size_t)kk*NPAD4 + b64];
        vh[j][0] = *(const uint4*)(pk + (size_t)i4.x*64 + gq*16);
        vh[j][1] = *(const uint4*)(pk + (size_t)i4.y*64 + gq*16);
        vh[j][2] = *(const uint4*)(pk + (size_t)i4.z*64 + gq*16);
        vh[j][3] = *(const uint4*)(pk + (size_t)i4.w*64 + gq*16);
    }
    {
        int kk = k0 + 2; if (kk >= KK) kk -= KK;
        iC = fidx4[(size_t)kk*NPAD4 + b64];
    }

    float acc[2][4][4];
    #pragma unroll
    for (int a = 0; a < 2; a++)
        #pragma unroll
        for (int b = 0; b < 4; b++)
            #pragma unroll
            for (int c = 0; c < 4; c++) acc[a][b][c] = 0.f;

    #pragma unroll 2
    for (int j = 0; j < KK; j++){
        const int buf = j & 1;
        int kk = k0 + j; if (kk >= KK) kk -= KK;

        // ---- snapshot fragments from arrived buffer ----
        unsigned ah[2][2][4];
        #pragma unroll
        for (int rb = 0; rb < 2; rb++){
            const unsigned* r0 = (const unsigned*)&vh[buf][2*rb];
            const unsigned* r1 = (const unsigned*)&vh[buf][2*rb+1];
            ah[rb][0][0]=r0[0]; ah[rb][0][1]=r1[0]; ah[rb][0][2]=r0[1]; ah[rb][0][3]=r1[1];
            ah[rb][1][0]=r0[2]; ah[rb][1][1]=r1[2]; ah[rb][1][2]=r0[3]; ah[rb][1][3]=r1[3];
        }

        // ---- issue j+2 into freed buffer ----
        if (j + 2 < KK){
            vh[buf][0] = *(const uint4*)(pk + (size_t)iC.x*64 + gq*16);
            vh[buf][1] = *(const uint4*)(pk + (size_t)iC.y*64 + gq*16);
            vh[buf][2] = *(const uint4*)(pk + (size_t)iC.z*64 + gq*16);
            vh[buf][3] = *(const uint4*)(pk + (size_t)iC.w*64 + gq*16);
        }
        // ---- preload idx for j+3 ----
        if (j + 3 < KK){
            int k3 = k0 + j + 3; if (k3 >= KK) k3 -= KK;
            iC = fidx4[(size_t)k3*NPAD4 + b64];
        }

        // ---- B per-nq + 16 mma ----
        const unsigned wk = sb + SM_W + kk*2048;
        #pragma unroll
        for (int nq = 0; nq < 4; nq++){
            unsigned bh[4];
            unsigned sw = ((((unsigned)nq) ^ ((lane>>1)&3)) << 4);
            ldmx4t(bh, wk + lane*64 + sw);
            #pragma unroll
            for (int rb = 0; rb < 2; rb++){
                mma16816h(acc[rb][nq], ah[rb][0], bh + 0);
                mma16816h(acc[rb][nq], ah[rb][1], bh + 2);
            }
        }
    }

    // ---- epilogue: fused BN stats + packed fp16 store ----
    float sR[8], qR[8];
    #pragma unroll
    for (int i = 0; i < 8; i++){ sR[i] = 0.f; qR[i] = 0.f; }

    #pragma unroll
    for (int rb = 0; rb < 2; rb++){
        #pragma unroll
        for (int nq = 0; nq < 4; nq++){
            float a0 = acc[rb][nq][0], a1 = acc[rb][nq][1];
            float a2 = acc[rb][nq][2], a3 = acc[rb][nq][3];
            sR[nq*2+0] += a0 + a2;  qR[nq*2+0] += a0*a0 + a2*a2;
            sR[nq*2+1] += a1 + a3;  qR[nq*2+1] += a1*a1 + a3*a3;
        }
    }
    #pragma unroll
    for (int rb = 0; rb < 2; rb++){
        int m0 = rbase + rb*16, m1 = m0 + 8;
        uint4 w0, w1;
        w0.x = pack_f16(acc[rb][0][0], acc[rb][0][1]);
        w0.y = pack_f16(acc[rb][1][0], acc[rb][1][1]);
        w0.z = pack_f16(acc[rb][2][0], acc[rb][2][1]);
        w0.w = pack_f16(acc[rb][3][0], acc[rb][3][1]);
        w1.x = pack_f16(acc[rb][0][2], acc[rb][0][3]);
        w1.y = pack_f16(acc[rb][1][2], acc[rb][1][3]);
        w1.z = pack_f16(acc[rb][2][2], acc[rb][2][3]);
        w1.w = pack_f16(acc[rb][3][2], acc[rb][3][3]);
        if (m0 < NP) ((uint4*)(outh + (size_t)m0*16))[gq] = w0;
        if (m1 < NP) ((uint4*)(outh + (size_t)m1*16))[gq] = w1;
    }
    #pragma unroll
    for (int i = 0; i < 8; i++){
        #pragma unroll
        for (int off = 4; off < 32; off <<= 1){
            sR[i] += __shfl_xor_sync(0xffffffffu, sR[i], off);
            qR[i] += __shfl_xor_sync(0xffffffffu, qR[i], off);
        }
    }
    if (lane < 4){
        float* st = (float*)(smem + SM_ST);
        #pragma unroll
        for (int nq = 0; nq < 4; nq++){
            atomicAdd(&st[     nq*8 + lane*2    ], sR[nq*2+0]);
            atomicAdd(&st[     nq*8 + lane*2 + 1], sR[nq*2+1]);
            atomicAdd(&st[32 + nq*8 + lane*2    ], qR[nq*2+0]);
            atomicAdd(&st[32 + nq*8 + lane*2 + 1], qR[nq*2+1]);
        }
    }
    __syncthreads();
    if (tid < 64) atomicAdd(&g_stats[stats_off + tid], ((float*)(smem + SM_ST))[tid]);
}

// ---- final: BN2(pkraw fp16) + residual(pkA fp16) + ReLU -> fp32 out ----
__global__ void bnrelu_kernel(const uint4* __restrict__ xh, const uint4* __restrict__ resh,
    int stats_off, const float* __restrict__ gamma, const float* __restrict__ beta,
    float* __restrict__ out)
{
    long long t = (long long)blockIdx.x*blockDim.x + threadIdx.x;
    if (t >= (long long)NP*4) return;
    const int g = (int)(t & 3);
    long long row = t >> 2;
    const float invN = 1.0f / NP;
    uint4 r  = xh[t];
    uint4 rr = resh[t];
    unsigned wv[4] = {r.x,  r.y,  r.z,  r.w};
    unsigned rv[4] = {rr.x, rr.y, rr.z, rr.w};
    #pragma unroll
    for (int i = 0; i < 4; i++){
        int c = 2*g + 8*i;
        float m0 = g_stats[stats_off + c]      * invN;
        float m1 = g_stats[stats_off + c + 1]  * invN;
        float v0 = g_stats[stats_off + 32 + c]     * invN - m0*m0;
        float v1 = g_stats[stats_off + 32 + c + 1] * invN - m1*m1;
        float s0 = rsqrtf(v0 + 1e-5f) * gamma[c];
        float s1 = rsqrtf(v1 + 1e-5f) * gamma[c+1];
        float2 f  = __half22float2(*(__half2*)&wv[i]);
        float2 rs = __half22float2(*(__half2*)&rv[i]);
        float o0 = fmaxf(f.x*s0 + (beta[c]   - m0*s0) + rs.x, 0.f);
        float o1 = fmaxf(f.y*s1 + (beta[c+1] - m1*s1) + rs.y, 0.f);
        __stcs((float2*)(out + row*CH + c), make_float2(o0, o1));
    }
}

extern "C" void kernel_launch(void* const* d_in, const int* in_sizes, int n_in,
                              void* d_out, int out_size)
{
    const float* feats  = (const float*)d_in[0];
    const float* W1     = (const float*)d_in[1];
    const float* gamma1 = (const float*)d_in[2];
    const float* beta1  = (const float*)d_in[3];
    const float* W2     = (const float*)d_in[4];
    const float* gamma2 = (const float*)d_in[5];
    const float* beta2  = (const float*)d_in[6];
    const int*   nbr    = (const int*)d_in[7];
    const int*   mask   = (const int*)d_in[8];
    float* out = (float*)d_out;

    unsigned short* wt; unsigned *pkA, *pkB, *pkraw; int4* fidx4;
    cudaGetSymbolAddress((void**)&wt,    g_wt);
    cudaGetSymbolAddress((void**)&pkA,   g_pkA);
    cudaGetSymbolAddress((void**)&pkB,   g_pkB);
    cudaGetSymbolAddress((void**)&pkraw, g_pkraw);
    cudaGetSymbolAddress((void**)&fidx4, g_fidx4);

    cudaFuncSetAttribute(conv_mma, cudaFuncAttributeMaxDynamicSharedMemorySize, SM_TOT);

    const int gridq = (int)(((long long)NP*4 + 255) / 256);

    prep_w<<<(2*KK*CH*CH + 255)/256, 256>>>(W1, W2);   // also zeroes stats + sentinel
    prep_fidx<<<NT2, 256>>>(nbr, mask, fidx4);
    // pack feats -> pkA; conv1: packed fp16 raw -> pkraw, stats@0
    pack_input<<<gridq, 256>>>(feats, (uint4*)pkA);
    conv_mma<<<NT, TPB, SM_TOT>>>((const unsigned char*)pkA, wt, fidx4, pkraw, 0);
    // BN1+ReLU -> pkB; conv2: packed fp16 raw -> pkraw, stats@64
    pack_bn<<<gridq, 256>>>((const uint4*)pkraw, (uint4*)pkB, gamma1, beta1);
    conv_mma<<<NT, TPB, SM_TOT>>>((const unsigned char*)pkB, wt + KK*1024, fidx4, pkraw, 64);
    // out = relu(BN2(pkraw) + pkA)
    bnrelu_kernel<<<gridq, 256>>>((const uint4*)pkraw, (const uint4*)pkA, 64,
                                  gamma2, beta2, out);
}